// round 6
// baseline (speedup 1.0000x reference)
#include <cuda_runtime.h>
#include <stdint.h>

#define BB 32
#define NGT 20
#define FH 64
#define FW 100
#define AA 9
#define HW (FH*FW)      // 6400
#define TT (HW*AA)      // 57600
#define FG_K 128
#define RPN_BATCH_K 256
#define FULLM 0xffffffffu

__device__ __constant__ float c_anchors[AA*4] = {
  -84.f,  -40.f,  99.f,  55.f,
 -176.f,  -88.f, 191.f, 103.f,
 -360.f, -184.f, 375.f, 199.f,
  -56.f,  -56.f,  71.f,  71.f,
 -120.f, -120.f, 135.f, 135.f,
 -248.f, -248.f, 263.f, 263.f,
  -36.f,  -80.f,  51.f,  95.f,
  -80.f, -168.f,  95.f, 183.f,
 -168.f, -344.f, 183.f, 359.f
};

// ---------------- Threefry-2x32 (20 rounds), matches JAX partitionable ----------------
__host__ __device__ __forceinline__ void tf2x32(uint32_t k0, uint32_t k1,
                                                uint32_t x0, uint32_t x1,
                                                uint32_t& o0, uint32_t& o1) {
  uint32_t ks2 = k0 ^ k1 ^ 0x1BD11BDAu;
  x0 += k0; x1 += k1;
#define TF_RND(r) { x0 += x1; x1 = (x1 << (r)) | (x1 >> (32 - (r))); x1 ^= x0; }
  TF_RND(13) TF_RND(15) TF_RND(26) TF_RND(6)   x0 += k1;  x1 += ks2 + 1u;
  TF_RND(17) TF_RND(29) TF_RND(16) TF_RND(24)  x0 += ks2; x1 += k0  + 2u;
  TF_RND(13) TF_RND(15) TF_RND(26) TF_RND(6)   x0 += k0;  x1 += k1  + 3u;
  TF_RND(17) TF_RND(29) TF_RND(16) TF_RND(24)  x0 += k1;  x1 += ks2 + 4u;
  TF_RND(13) TF_RND(15) TF_RND(26) TF_RND(6)   x0 += ks2; x1 += k0  + 5u;
#undef TF_RND
  o0 = x0; o1 = x1;
}

// ---------------- scratch (device globals; no allocations) ----------------
__device__ unsigned int        g_gtmax[BB*NGT];  // biased-float max of positive IoUs (0 = none)
__device__ int                 g_cnt_fg[BB];
__device__ int                 g_cnt_bg[BB];
__device__ unsigned char       g_lab[BB*TT];     // s = a*HW+hw order; 0=bg,1=fg,2=dontcare
__device__ unsigned long long  g_cfg[(size_t)BB*TT];  // fg candidate keys (m<<16)|t
__device__ unsigned long long  g_cbg[(size_t)BB*TT];  // bg candidate keys
__device__ float               g_uw[BB];

// ---------------- K0: zero tiny scratch ----------------
__global__ void k0_zero() {
  int i = threadIdx.x;
  if (i < BB*NGT) g_gtmax[i] = 0u;
  if (i < BB) { g_cnt_fg[i] = 0; g_cnt_bg[i] = 0; }
}

// ---------------- K1: per-(b,g) max of positive IoUs ----------------
__global__ void k1_gtmax(const float* __restrict__ gt, const float* __restrict__ iminfo) {
  __shared__ float    s_gt[NGT*5];
  __shared__ unsigned s_max[NGT];
  int b = blockIdx.z, a = blockIdx.y, tid = threadIdx.x;
  int hw = blockIdx.x * 256 + tid;
  if (tid < NGT*5) s_gt[tid] = gt[b*NGT*5 + tid];
  if (tid < NGT)   s_max[tid] = 0u;
  __syncthreads();
  float img_h = iminfo[0], img_w = iminfo[1];
  int h = hw / FW, w = hw - h * FW;
  float sx = (float)(w * 16), sy = (float)(h * 16);
  float ax1 = c_anchors[a*4+0] + sx;
  float ay1 = c_anchors[a*4+1] + sy;
  float ax2 = c_anchors[a*4+2] + sx;
  float ay2 = c_anchors[a*4+3] + sy;
  bool inside = (ax1 >= 0.f) && (ay1 >= 0.f) && (ax2 < img_w) && (ay2 < img_h);
  float aw = __fadd_rn(__fsub_rn(ax2, ax1), 1.0f);
  float ah = __fadd_rn(__fsub_rn(ay2, ay1), 1.0f);
  float area = __fmul_rn(aw, ah);

  if (__ballot_sync(FULLM, inside)) {
    for (int g = 0; g < NGT; g++) {
      float gx1 = s_gt[g*5+0], gy1 = s_gt[g*5+1], gx2 = s_gt[g*5+2], gy2 = s_gt[g*5+3];
      float gw = __fadd_rn(__fsub_rn(gx2, gx1), 1.0f);
      float gh = __fadd_rn(__fsub_rn(gy2, gy1), 1.0f);
      bool gz = (gw == 1.0f) && (gh == 1.0f);
      float iw = __fadd_rn(__fsub_rn(fminf(ax2, gx2), fmaxf(ax1, gx1)), 1.0f);
      float ih = __fadd_rn(__fsub_rn(fminf(ay2, gy2), fmaxf(ay1, gy1)), 1.0f);
      float inter = __fmul_rn(fmaxf(iw, 0.0f), fmaxf(ih, 0.0f));
      bool need = inside && !gz && (inter > 0.0f);
      if (__ballot_sync(FULLM, need)) {
        unsigned fu = 0u;
        if (need) {
          float ga = __fmul_rn(gw, gh);
          float ua = __fsub_rn(__fadd_rn(area, ga), inter);
          float v  = __fdiv_rn(inter, ua);           // > 0
          fu = __float_as_uint(v) | 0x80000000u;     // order-preserving for positives
        }
        unsigned r = __reduce_max_sync(FULLM, fu);
        if ((tid & 31) == 0) atomicMax(&s_max[g], r);
      }
    }
  }
  __syncthreads();
  if (tid < NGT && s_max[tid]) atomicMax(&g_gtmax[b*NGT + tid], s_max[tid]);
}

// ---------------- K2: labels, targets -> out, RNG + compaction ----------------
__global__ void k2_main(const float* __restrict__ gt, const float* __restrict__ iminfo,
                        uint32_t kf0, uint32_t kf1, uint32_t kb0, uint32_t kb1,
                        float* __restrict__ out) {
  __shared__ float s_gt[NGT*5];
  __shared__ float s_gm[NGT];
  int b = blockIdx.z, a = blockIdx.y, tid = threadIdx.x;
  int hw = blockIdx.x * 256 + tid;
  if (tid < NGT*5) s_gt[tid] = gt[b*NGT*5 + tid];
  if (tid < NGT) {
    unsigned u_ = g_gtmax[b*NGT + tid];
    s_gm[tid] = u_ ? __uint_as_float(u_ ^ 0x80000000u) : -999.0f;
  }
  __syncthreads();
  float img_h = iminfo[0], img_w = iminfo[1];
  int h = hw / FW, w = hw - h * FW;
  float sx = (float)(w * 16), sy = (float)(h * 16);
  float ax1 = c_anchors[a*4+0] + sx;
  float ay1 = c_anchors[a*4+1] + sy;
  float ax2 = c_anchors[a*4+2] + sx;
  float ay2 = c_anchors[a*4+3] + sy;
  bool inside = (ax1 >= 0.f) && (ay1 >= 0.f) && (ax2 < img_w) && (ay2 < img_h);
  float aw = __fadd_rn(__fsub_rn(ax2, ax1), 1.0f);
  float ah = __fadd_rn(__fsub_rn(ay2, ay1), 1.0f);
  float area = __fmul_rn(aw, ah);

  float mx = -3.0f; int amax = 0; bool keep = false;
  if (__ballot_sync(FULLM, inside)) {
    for (int g = 0; g < NGT; g++) {
      float gx1 = s_gt[g*5+0], gy1 = s_gt[g*5+1], gx2 = s_gt[g*5+2], gy2 = s_gt[g*5+3];
      float gw = __fadd_rn(__fsub_rn(gx2, gx1), 1.0f);
      float gh = __fadd_rn(__fsub_rn(gy2, gy1), 1.0f);
      bool gz = (gw == 1.0f) && (gh == 1.0f);
      float iw = __fadd_rn(__fsub_rn(fminf(ax2, gx2), fmaxf(ax1, gx1)), 1.0f);
      float ih = __fadd_rn(__fsub_rn(fminf(ay2, gy2), fmaxf(ay1, gy1)), 1.0f);
      float inter = __fmul_rn(fmaxf(iw, 0.0f), fmaxf(ih, 0.0f));
      bool need = inside && !gz && (inter > 0.0f);
      float v = 0.0f;
      if (__ballot_sync(FULLM, need)) {
        if (need) {
          float ga = __fmul_rn(gw, gh);
          float ua = __fsub_rn(__fadd_rn(area, ga), inter);
          v = __fdiv_rn(inter, ua);
        }
      }
      keep = keep || (v == s_gm[g]);
      if (v > mx) { mx = v; amax = g; }   // first-occurrence argmax
    }
  }

  unsigned char L = 2;
  if (inside) L = (keep || mx >= 0.7f) ? 1 : ((mx < 0.3f) ? 0 : 2);
  size_t sidx = (size_t)b * TT + a * HW + hw;
  g_lab[sidx] = L;

  // bbox targets straight into output (coalesced planes)
  float4 tg = make_float4(0.f, 0.f, 0.f, 0.f);
  if (inside) {
    const float* g5 = &s_gt[amax*5];
    float ew = ax2 - ax1 + 1.0f, eh = ay2 - ay1 + 1.0f;
    float ecx = ax1 + 0.5f*ew,   ecy = ay1 + 0.5f*eh;
    float gw = g5[2] - g5[0] + 1.0f, gh = g5[3] - g5[1] + 1.0f;
    float gcx = g5[0] + 0.5f*gw,     gcy = g5[1] + 0.5f*gh;
    tg.x = (gcx - ecx) / ew;
    tg.y = (gcy - ecy) / eh;
    tg.z = logf(gw / ew);
    tg.w = logf(gh / eh);
  }
  float* tgt_o = out + (size_t)BB * AA * HW;
  size_t cb = ((size_t)b * 36 + a * 4) * HW + hw;
  tgt_o[cb        ] = tg.x;
  tgt_o[cb +   HW ] = tg.y;
  tgt_o[cb + 2*HW ] = tg.z;
  tgt_o[cb + 3*HW ] = tg.w;

  // RNG draw + warp-aggregated compaction of candidate keys
  unsigned ballot_fg = __ballot_sync(FULLM, L == 1);
  unsigned ballot_bg = __ballot_sync(FULLM, L == 0);
  unsigned long long key = 0ull;
  int t = hw * 9 + a;                      // original anchor index (t-order)
  if (L <= 1) {
    uint32_t key0 = L ? kf0 : kb0, key1 = L ? kf1 : kb1;
    uint32_t o0, o1;
    uint32_t cnt = (uint32_t)(b * TT + t);
    tf2x32(key0, key1, 0u, cnt, o0, o1);
    unsigned m = (o0 ^ o1) >> 9;           // 23-bit, monotone in uniform
    key = ((unsigned long long)m << 16) | (unsigned)t;   // unique 39-bit key
  }
  int lane = tid & 31;
  if (L == 1) {
    unsigned mask = ballot_fg;
    int leader = __ffs(mask) - 1;
    int base = 0;
    if (lane == leader) base = atomicAdd(&g_cnt_fg[b], __popc(mask));
    base = __shfl_sync(mask, base, leader);
    int off = __popc(mask & ((1u << lane) - 1u));
    g_cfg[(size_t)b * TT + base + off] = key;
  } else if (L == 0) {
    unsigned mask = ballot_bg;
    int leader = __ffs(mask) - 1;
    int base = 0;
    if (lane == leader) base = atomicAdd(&g_cnt_bg[b], __popc(mask));
    base = __shfl_sync(mask, base, leader);
    int off = __popc(mask & ((1u << lane) - 1u));
    g_cbg[(size_t)b * TT + base + off] = key;
  }
}

// ---------------- K3: exact radix select on 39-bit keys ----------------
__device__ __forceinline__ int blockInclScan(int local, int* s_wsum) {
  int lane = threadIdx.x & 31, wid = threadIdx.x >> 5;
  int v = local;
#pragma unroll
  for (int o = 1; o < 32; o <<= 1) { int n = __shfl_up_sync(FULLM, v, o); if (lane >= o) v += n; }
  if (lane == 31) s_wsum[wid] = v;
  __syncthreads();
  if (wid == 0) {
    int wv = s_wsum[lane];
#pragma unroll
    for (int o = 1; o < 32; o <<= 1) { int n = __shfl_up_sync(FULLM, wv, o); if (lane >= o) wv += n; }
    s_wsum[lane] = wv;
  }
  __syncthreads();
  return v + (wid ? s_wsum[wid-1] : 0);
}

__global__ void __launch_bounds__(1024) k3_select() {
  __shared__ unsigned s_hist[8192];
  __shared__ int s_wsum[32];
  __shared__ int s_sel[2];   // {bin, cumBefore}
  int b = blockIdx.x, cls = blockIdx.y, tid = threadIdx.x;

  int nfg = g_cnt_fg[b];
  int n   = cls ? nfg : g_cnt_bg[b];
  int kept_fg = min(nfg, FG_K);
  int k = cls ? FG_K : (RPN_BATCH_K - kept_fg);
  if (cls == 0 && tid == 0)
    g_uw[b] = 1.0f / (float)(kept_fg + min(n, k));
  if (n <= k) return;

  const unsigned long long* keys = (cls ? g_cfg : g_cbg) + (size_t)b * TT;
  unsigned char* lab = g_lab + (size_t)b * TT;

  unsigned long long prefix = 0ull;
  int kk = k;
#pragma unroll
  for (int lvl = 0; lvl < 3; lvl++) {
    int shift = 26 - 13 * lvl;
    for (int i = tid; i < 8192; i += 1024) s_hist[i] = 0u;
    __syncthreads();
    for (int i = tid; i < n; i += 1024) {
      unsigned long long key = keys[i];
      if (lvl == 0 || (key >> (shift + 13)) == prefix)
        atomicAdd(&s_hist[(unsigned)(key >> shift) & 8191u], 1u);
    }
    __syncthreads();
    int base = tid * 8;
    int local = 0;
#pragma unroll
    for (int j = 0; j < 8; j++) local += (int)s_hist[base + j];
    int incl = blockInclScan(local, s_wsum);
    int excl = incl - local;
    if (kk > excl && kk <= incl) {
      int c = excl;
      for (int j = 0; j < 8; j++) {
        int hh = (int)s_hist[base + j];
        if (c + hh >= kk) { s_sel[0] = base + j; s_sel[1] = c; break; }
        c += hh;
      }
    }
    __syncthreads();
    prefix = (prefix << 13) | (unsigned)s_sel[0];
    kk -= s_sel[1];
    __syncthreads();
  }
  unsigned long long kstar = prefix;   // exact k-th smallest key (keys unique)

  // demote everything above the threshold
  for (int i = tid; i < n; i += 1024) {
    unsigned long long key = keys[i];
    if (key > kstar) {
      int t = (int)(key & 0xFFFFull);
      lab[(t % 9) * HW + t / 9] = 2;
    }
  }
}

// ---------------- K4: labels + in/out weights (vectorized) ----------------
__global__ void k4_out(float* __restrict__ out) {
  int idx = blockIdx.x * 320 + threadIdx.x;   // 0..1599
  int b = blockIdx.y;
  int hw = idx * 4;
  float u = g_uw[b];
  const size_t OFF1 = (size_t)BB * AA * HW;
  const size_t PL   = (size_t)BB * 36 * HW;
  float* lab_o  = out;
  float* inw_o  = out + OFF1 + PL;
  float* outw_o = out + OFF1 + 2 * PL;
#pragma unroll
  for (int a = 0; a < AA; a++) {
    uchar4 L4 = *reinterpret_cast<const uchar4*>(&g_lab[(size_t)b * TT + a * HW + hw]);
    float4 lv, iw, ow;
    lv.x = (L4.x == 2) ? -1.f : (float)L4.x;
    lv.y = (L4.y == 2) ? -1.f : (float)L4.y;
    lv.z = (L4.z == 2) ? -1.f : (float)L4.z;
    lv.w = (L4.w == 2) ? -1.f : (float)L4.w;
    iw.x = (L4.x == 1) ? 1.f : 0.f;
    iw.y = (L4.y == 1) ? 1.f : 0.f;
    iw.z = (L4.z == 1) ? 1.f : 0.f;
    iw.w = (L4.w == 1) ? 1.f : 0.f;
    ow.x = (L4.x != 2) ? u : 0.f;
    ow.y = (L4.y != 2) ? u : 0.f;
    ow.z = (L4.z != 2) ? u : 0.f;
    ow.w = (L4.w != 2) ? u : 0.f;
    *reinterpret_cast<float4*>(&lab_o[((size_t)b * AA + a) * HW + hw]) = lv;
    size_t cbase = ((size_t)b * 36 + a * 4) * HW + hw;
#pragma unroll
    for (int c = 0; c < 4; c++) {
      *reinterpret_cast<float4*>(&inw_o [cbase + (size_t)c * HW]) = iw;
      *reinterpret_cast<float4*>(&outw_o[cbase + (size_t)c * HW]) = ow;
    }
  }
}

// ---------------- host ----------------
extern "C" void kernel_launch(void* const* d_in, const int* in_sizes, int n_in,
                              void* d_out, int out_size) {
  const float* gt     = (const float*)d_in[1];   // gt_boxes [32,20,5]
  const float* iminfo = (const float*)d_in[2];   // im_info [32,3]
  float* out = (float*)d_out;

  uint32_t kf0, kf1, kb0, kb1;
  tf2x32(0u, 42u, 0u, 0u, kf0, kf1);
  tf2x32(0u, 42u, 0u, 1u, kb0, kb1);

  k0_zero  <<<1, 1024>>>();
  k1_gtmax <<<dim3(HW/256, AA, BB), 256>>>(gt, iminfo);
  k2_main  <<<dim3(HW/256, AA, BB), 256>>>(gt, iminfo, kf0, kf1, kb0, kb1, out);
  k3_select<<<dim3(BB, 2), 1024>>>();
  k4_out   <<<dim3(5, BB), 320>>>(out);
}

// round 7
// speedup vs baseline: 1.3267x; 1.3267x over previous
#include <cuda_runtime.h>
#include <stdint.h>

#define BB 32
#define NGT 20
#define FH 64
#define FW 100
#define AA 9
#define HW (FH*FW)      // 6400
#define TT (HW*AA)      // 57600
#define FG_K 128
#define RPN_BATCH_K 256
#define FULLM 0xffffffffu

__device__ __constant__ float c_anchors[AA*4] = {
  -84.f,  -40.f,  99.f,  55.f,
 -176.f,  -88.f, 191.f, 103.f,
 -360.f, -184.f, 375.f, 199.f,
  -56.f,  -56.f,  71.f,  71.f,
 -120.f, -120.f, 135.f, 135.f,
 -248.f, -248.f, 263.f, 263.f,
  -36.f,  -80.f,  51.f,  95.f,
  -80.f, -168.f,  95.f, 183.f,
 -168.f, -344.f, 183.f, 359.f
};

// ---------------- Threefry-2x32 (20 rounds), matches JAX partitionable ----------------
__host__ __device__ __forceinline__ void tf2x32(uint32_t k0, uint32_t k1,
                                                uint32_t x0, uint32_t x1,
                                                uint32_t& o0, uint32_t& o1) {
  uint32_t ks2 = k0 ^ k1 ^ 0x1BD11BDAu;
  x0 += k0; x1 += k1;
#define TF_RND(r) { x0 += x1; x1 = (x1 << (r)) | (x1 >> (32 - (r))); x1 ^= x0; }
  TF_RND(13) TF_RND(15) TF_RND(26) TF_RND(6)   x0 += k1;  x1 += ks2 + 1u;
  TF_RND(17) TF_RND(29) TF_RND(16) TF_RND(24)  x0 += ks2; x1 += k0  + 2u;
  TF_RND(13) TF_RND(15) TF_RND(26) TF_RND(6)   x0 += k0;  x1 += k1  + 3u;
  TF_RND(17) TF_RND(29) TF_RND(16) TF_RND(24)  x0 += k1;  x1 += ks2 + 4u;
  TF_RND(13) TF_RND(15) TF_RND(26) TF_RND(6)   x0 += ks2; x1 += k0  + 5u;
#undef TF_RND
  o0 = x0; o1 = x1;
}

// ---------------- scratch (device globals; no allocations) ----------------
__device__ unsigned int        g_gtmax[BB*NGT];  // biased-float max of positive IoUs (0 = none)
__device__ int                 g_cnt_fg[BB];
__device__ int                 g_cnt_bg[BB];
__device__ int                 g_nkept[BB];
__device__ int                 g_kept[BB*256];   // (cls<<16) | t
__device__ unsigned long long  g_cfg[(size_t)BB*TT];  // fg candidate keys (m<<16)|t
__device__ unsigned long long  g_cbg[(size_t)BB*TT];  // bg candidate keys
__device__ float               g_uw[BB];

// ---------------- KF: constant fill of labels / in_w / out_w ----------------
__global__ void kfill(float* __restrict__ out) {
  // labels: float4 [0, 460800)  value -1 ; weights: float4 [2304000, 5990400) value 0
  int i = blockIdx.x * 1024 + threadIdx.x;   // 0 .. 4,147,199
  float4* o4 = reinterpret_cast<float4*>(out);
  if (i < 460800) {
    o4[i] = make_float4(-1.f, -1.f, -1.f, -1.f);
  } else {
    o4[i + 1843200] = make_float4(0.f, 0.f, 0.f, 0.f);
  }
}

// ---------------- K1: gt-centric per-(b,g) max of positive inside IoUs ----------------
__global__ void k1_gtmax(const float* __restrict__ gt, const float* __restrict__ iminfo) {
  int g = blockIdx.x, b = blockIdx.y, tid = threadIdx.x;
  if (g == 0 && tid == 0) { g_cnt_fg[b] = 0; g_cnt_bg[b] = 0; g_nkept[b] = 0; }
  __shared__ unsigned s_best[8];
  float gx1 = __ldg(&gt[(b*NGT+g)*5+0]);
  float gy1 = __ldg(&gt[(b*NGT+g)*5+1]);
  float gx2 = __ldg(&gt[(b*NGT+g)*5+2]);
  float gy2 = __ldg(&gt[(b*NGT+g)*5+3]);
  float gw = __fadd_rn(__fsub_rn(gx2, gx1), 1.0f);
  float gh = __fadd_rn(__fsub_rn(gy2, gy1), 1.0f);
  if (gw == 1.0f && gh == 1.0f) {              // zero gt
    if (tid == 0) g_gtmax[b*NGT + g] = 0u;
    return;
  }
  float ga = __fmul_rn(gw, gh);
  float img_h = iminfo[0], img_w = iminfo[1];
  unsigned best = 0u;
  for (int a = 0; a < AA; a++) {
    float ax1_0 = c_anchors[a*4+0], ay1_0 = c_anchors[a*4+1];
    float ax2_0 = c_anchors[a*4+2], ay2_0 = c_anchors[a*4+3];
    // inside range ∩ (widened) overlap range
    int w0 = max(max((int)ceilf(-ax1_0 * 0.0625f),
                     (int)floorf((gx1 - ax2_0) * 0.0625f) - 1), 0);
    int w1 = min(min((int)floorf((img_w - 1.0f - ax2_0) * 0.0625f),
                     (int)ceilf((gx2 - ax1_0) * 0.0625f) + 1), FW-1);
    int h0 = max(max((int)ceilf(-ay1_0 * 0.0625f),
                     (int)floorf((gy1 - ay2_0) * 0.0625f) - 1), 0);
    int h1 = min(min((int)floorf((img_h - 1.0f - ay2_0) * 0.0625f),
                     (int)ceilf((gy2 - ay1_0) * 0.0625f) + 1), FH-1);
    if (w1 < w0 || h1 < h0) continue;
    int nw = w1 - w0 + 1, cnt = nw * (h1 - h0 + 1);
    float aw = __fadd_rn(__fsub_rn(ax2_0, ax1_0), 1.0f);   // exact, == per-pos value
    float ah = __fadd_rn(__fsub_rn(ay2_0, ay1_0), 1.0f);
    float area = __fmul_rn(aw, ah);
    for (int i = tid; i < cnt; i += 256) {
      int w = w0 + i % nw, h = h0 + i / nw;
      float sx = 16.f * (float)w, sy = 16.f * (float)h;
      float ax1 = ax1_0 + sx, ax2 = ax2_0 + sx;
      float ay1 = ay1_0 + sy, ay2 = ay2_0 + sy;
      float iw = __fadd_rn(__fsub_rn(fminf(ax2, gx2), fmaxf(ax1, gx1)), 1.0f);
      float ih = __fadd_rn(__fsub_rn(fminf(ay2, gy2), fmaxf(ay1, gy1)), 1.0f);
      float inter = __fmul_rn(fmaxf(iw, 0.0f), fmaxf(ih, 0.0f));
      if (inter > 0.0f) {
        float ua = __fsub_rn(__fadd_rn(area, ga), inter);
        float v  = __fdiv_rn(inter, ua);
        unsigned fu = __float_as_uint(v) | 0x80000000u;
        best = max(best, fu);
      }
    }
  }
  best = __reduce_max_sync(FULLM, best);
  if ((tid & 31) == 0) s_best[tid >> 5] = best;
  __syncthreads();
  if (tid == 0) {
    unsigned m = 0u;
#pragma unroll
    for (int i = 0; i < 8; i++) m = max(m, s_best[i]);
    g_gtmax[b*NGT + g] = m;
  }
}

// ---------------- K2: labels(implicit), targets -> out, RNG + compaction ----------------
__global__ void k2_main(const float* __restrict__ gt, const float* __restrict__ iminfo,
                        uint32_t kf0, uint32_t kf1, uint32_t kb0, uint32_t kb1,
                        float* __restrict__ out) {
  __shared__ float s_gx1[NGT], s_gy1[NGT], s_gx2[NGT], s_gy2[NGT];
  __shared__ float s_ga[NGT], s_gcx[NGT], s_gcy[NGT], s_lw[NGT], s_lh[NGT], s_gm[NGT];
  __shared__ int s_gl[NGT];
  __shared__ int s_ng;
  int b = blockIdx.z, a = blockIdx.y, tid = threadIdx.x;
  int hw = blockIdx.x * 256 + tid;

  // per-block anchor-shape constants
  float ax1_0 = c_anchors[a*4+0], ay1_0 = c_anchors[a*4+1];
  float ax2_0 = c_anchors[a*4+2], ay2_0 = c_anchors[a*4+3];
  float ew = __fadd_rn(__fsub_rn(ax2_0, ax1_0), 1.0f);
  float eh = __fadd_rn(__fsub_rn(ay2_0, ay1_0), 1.0f);
  float area = __fmul_rn(ew, eh);

  if (tid < 32) {
    bool nz = false;
    if (tid < NGT) {
      float x1 = gt[(b*NGT+tid)*5+0], y1 = gt[(b*NGT+tid)*5+1];
      float x2 = gt[(b*NGT+tid)*5+2], y2 = gt[(b*NGT+tid)*5+3];
      float gw = __fadd_rn(__fsub_rn(x2, x1), 1.0f);
      float gh = __fadd_rn(__fsub_rn(y2, y1), 1.0f);
      nz = !(gw == 1.0f && gh == 1.0f);
      s_gx1[tid] = x1; s_gy1[tid] = y1; s_gx2[tid] = x2; s_gy2[tid] = y2;
      s_ga[tid]  = __fmul_rn(gw, gh);
      s_gcx[tid] = x1 + 0.5f * gw;
      s_gcy[tid] = y1 + 0.5f * gh;
      s_lw[tid]  = logf(gw / ew);
      s_lh[tid]  = logf(gh / eh);
      unsigned u_ = g_gtmax[b*NGT + tid];
      s_gm[tid]  = u_ ? __uint_as_float(u_ ^ 0x80000000u) : -999.0f;
    }
    unsigned mask = __ballot_sync(FULLM, nz);
    if (tid == 0) s_ng = __popc(mask);
    if (nz) s_gl[__popc(mask & ((1u << tid) - 1u))] = tid;
  }
  __syncthreads();

  float img_h = iminfo[0], img_w = iminfo[1];
  int h = hw / FW, w = hw - h * FW;
  float sx = (float)(w * 16), sy = (float)(h * 16);
  float ax1 = ax1_0 + sx, ax2 = ax2_0 + sx;
  float ay1 = ay1_0 + sy, ay2 = ay2_0 + sy;
  bool inside = (ax1 >= 0.f) && (ay1 >= 0.f) && (ax2 < img_w) && (ay2 < img_h);

  float mx = 0.0f; int amax = 0; bool keep = false;
  if (__ballot_sync(FULLM, inside)) {
    int ng = s_ng;
    for (int gi = 0; gi < ng; gi++) {
      int g = s_gl[gi];
      float iw = __fadd_rn(__fsub_rn(fminf(ax2, s_gx2[g]), fmaxf(ax1, s_gx1[g])), 1.0f);
      float ih = __fadd_rn(__fsub_rn(fminf(ay2, s_gy2[g]), fmaxf(ay1, s_gy1[g])), 1.0f);
      float inter = __fmul_rn(fmaxf(iw, 0.0f), fmaxf(ih, 0.0f));
      bool need = inside && (inter > 0.0f);
      float v = 0.0f;
      if (__ballot_sync(FULLM, need)) {
        if (need) {
          float ua = __fsub_rn(__fadd_rn(area, s_ga[g]), inter);
          v = __fdiv_rn(inter, ua);
        }
      }
      keep = keep || (v == s_gm[g]);
      if (v > mx) { mx = v; amax = g; }   // first-occurrence argmax (zero gts give 0)
    }
  }

  int L = 2;   // dontcare
  if (inside) L = (keep || mx >= 0.7f) ? 1 : ((mx < 0.3f) ? 0 : 2);

  // bbox targets straight into output (coalesced planes)
  float4 tg = make_float4(0.f, 0.f, 0.f, 0.f);
  if (inside) {
    float ecx = ax1 + 0.5f * ew, ecy = ay1 + 0.5f * eh;
    tg.x = (s_gcx[amax] - ecx) / ew;
    tg.y = (s_gcy[amax] - ecy) / eh;
    tg.z = s_lw[amax];
    tg.w = s_lh[amax];
  }
  float* tgt_o = out + (size_t)BB * AA * HW;
  size_t cb = ((size_t)b * 36 + a * 4) * HW + hw;
  tgt_o[cb        ] = tg.x;
  tgt_o[cb +   HW ] = tg.y;
  tgt_o[cb + 2*HW ] = tg.z;
  tgt_o[cb + 3*HW ] = tg.w;

  // RNG draw + warp-aggregated compaction of candidate keys
  unsigned ballot_fg = __ballot_sync(FULLM, L == 1);
  unsigned ballot_bg = __ballot_sync(FULLM, L == 0);
  unsigned long long key = 0ull;
  int t = hw * 9 + a;                      // original anchor index (t-order)
  if (L <= 1) {
    uint32_t key0 = L ? kf0 : kb0, key1 = L ? kf1 : kb1;
    uint32_t o0, o1;
    uint32_t cntc = (uint32_t)(b * TT + t);
    tf2x32(key0, key1, 0u, cntc, o0, o1);
    unsigned m = (o0 ^ o1) >> 9;           // 23-bit, monotone in uniform
    key = ((unsigned long long)m << 16) | (unsigned)t;   // unique 39-bit key
  }
  int lane = tid & 31;
  if (L == 1) {
    unsigned mask = ballot_fg;
    int leader = __ffs(mask) - 1;
    int base = 0;
    if (lane == leader) base = atomicAdd(&g_cnt_fg[b], __popc(mask));
    base = __shfl_sync(mask, base, leader);
    int off = __popc(mask & ((1u << lane) - 1u));
    g_cfg[(size_t)b * TT + base + off] = key;
  } else if (L == 0) {
    unsigned mask = ballot_bg;
    int leader = __ffs(mask) - 1;
    int base = 0;
    if (lane == leader) base = atomicAdd(&g_cnt_bg[b], __popc(mask));
    base = __shfl_sync(mask, base, leader);
    int off = __popc(mask & ((1u << lane) - 1u));
    g_cbg[(size_t)b * TT + base + off] = key;
  }
}

// ---------------- K3: exact k-smallest -> kept list ----------------
__device__ __forceinline__ int blockInclScan(int local, int* s_wsum) {
  int lane = threadIdx.x & 31, wid = threadIdx.x >> 5;
  int v = local;
#pragma unroll
  for (int o = 1; o < 32; o <<= 1) { int n = __shfl_up_sync(FULLM, v, o); if (lane >= o) v += n; }
  if (lane == 31) s_wsum[wid] = v;
  __syncthreads();
  if (wid == 0) {
    int wv = s_wsum[lane];
#pragma unroll
    for (int o = 1; o < 32; o <<= 1) { int n = __shfl_up_sync(FULLM, wv, o); if (lane >= o) wv += n; }
    s_wsum[lane] = wv;
  }
  __syncthreads();
  return v + (wid ? s_wsum[wid-1] : 0);
}

__global__ void __launch_bounds__(1024) k3_select() {
  __shared__ unsigned s_hist[8192];
  __shared__ int s_wsum[32];
  __shared__ int s_sel[2];
  __shared__ int s_cnt;
  unsigned long long* s_keys = reinterpret_cast<unsigned long long*>(s_hist); // overlay, cap 4096
  int b = blockIdx.x, cls = blockIdx.y, tid = threadIdx.x;

  int nfg = g_cnt_fg[b];
  int n   = cls ? nfg : g_cnt_bg[b];
  int kept_fg = min(nfg, FG_K);
  int k = cls ? FG_K : (RPN_BATCH_K - kept_fg);
  if (cls == 0 && tid == 0)
    g_uw[b] = 1.0f / (float)(kept_fg + min(n, k));
  const unsigned long long* keys = (cls ? g_cfg : g_cbg) + (size_t)b * TT;

  if (n <= k) {                      // keep everything
    for (int i = tid; i < n; i += 1024) {
      int e = (int)(keys[i] & 0xFFFFull) | (cls << 16);
      int j = atomicAdd(&g_nkept[b], 1);
      g_kept[b*256 + j] = e;
    }
    return;
  }

  unsigned long long prefix = 0ull;
  int kk = k, shift = 26;
  for (int lvl = 0; ; lvl++) {
    shift = 26 - 13 * lvl;
    for (int i = tid; i < 8192; i += 1024) s_hist[i] = 0u;
    __syncthreads();
    for (int i = tid; i < n; i += 1024) {
      unsigned long long key = keys[i];
      if (lvl == 0 || (key >> (shift + 13)) == prefix)
        atomicAdd(&s_hist[(unsigned)(key >> shift) & 8191u], 1u);
    }
    __syncthreads();
    { // select bin containing kk-th
      int base = tid * 8, local = 0;
#pragma unroll
      for (int j = 0; j < 8; j++) local += (int)s_hist[base + j];
      int incl = blockInclScan(local, s_wsum);
      int excl = incl - local;
      if (kk > excl && kk <= incl) {
        int c = excl;
        for (int j = 0; j < 8; j++) {
          int hh = (int)s_hist[base + j];
          if (c + hh >= kk) { s_sel[0] = base + j; s_sel[1] = c; break; }
          c += hh;
        }
      }
      __syncthreads();
    }
    prefix = (prefix << 13) | (unsigned)s_sel[0];
    kk -= s_sel[1];
    int bc = (int)s_hist[s_sel[0]];
    __syncthreads();
    if (bc <= 4096 || shift == 0) break;   // shift==0 => bc==1 (keys unique)
  }

  // collect candidates (== prefix) and keep all keys strictly below prefix
  if (tid == 0) s_cnt = 0;
  __syncthreads();
  for (int i = tid; i < n; i += 1024) {
    unsigned long long key = keys[i];
    unsigned long long hi = key >> shift;
    if (hi < prefix) {
      int j = atomicAdd(&g_nkept[b], 1);
      g_kept[b*256 + j] = (int)(key & 0xFFFFull) | (cls << 16);
    } else if (hi == prefix) {
      int j = atomicAdd(&s_cnt, 1);
      s_keys[j] = key;
    }
  }
  __syncthreads();
  int cnt = s_cnt;                   // == bin count <= 4096
  for (int jj = tid; jj < cnt; jj += 1024) {
    unsigned long long kj = s_keys[jj];
    int r = 0;
    for (int i = 0; i < cnt; i++) r += (s_keys[i] < kj);
    if (r < kk) {                    // kk smallest candidates are kept
      int j = atomicAdd(&g_nkept[b], 1);
      g_kept[b*256 + j] = (int)(kj & 0xFFFFull) | (cls << 16);
    }
  }
}

// ---------------- K5: scatter kept anchors into output ----------------
__global__ void k5_scatter(float* __restrict__ out) {
  int b = blockIdx.x, tid = threadIdx.x;
  int nk = g_nkept[b];
  float u = g_uw[b];
  const size_t OFF1 = (size_t)BB * AA * HW;
  const size_t PL   = (size_t)BB * 36 * HW;
  float* inw_o  = out + OFF1 + PL;
  float* outw_o = out + OFF1 + 2 * PL;
  for (int i = tid; i < nk; i += 256) {
    int e = g_kept[b*256 + i];
    int t = e & 0xFFFF, cls = e >> 16;
    int a = t % 9, hw = t / 9;
    out[((size_t)b * AA + a) * HW + hw] = (float)cls;   // label 1 or 0
    size_t cb = ((size_t)b * 36 + a * 4) * HW + hw;
    if (cls) {
#pragma unroll
      for (int c = 0; c < 4; c++) inw_o[cb + (size_t)c * HW] = 1.0f;
    }
#pragma unroll
    for (int c = 0; c < 4; c++) outw_o[cb + (size_t)c * HW] = u;
  }
}

// ---------------- host ----------------
extern "C" void kernel_launch(void* const* d_in, const int* in_sizes, int n_in,
                              void* d_out, int out_size) {
  const float* gt     = (const float*)d_in[1];   // gt_boxes [32,20,5]
  const float* iminfo = (const float*)d_in[2];   // im_info [32,3]
  float* out = (float*)d_out;

  uint32_t kf0, kf1, kb0, kb1;
  tf2x32(0u, 42u, 0u, 0u, kf0, kf1);
  tf2x32(0u, 42u, 0u, 1u, kb0, kb1);

  kfill    <<<4050, 1024>>>(out);                       // 4050*1024 == 4,147,200 exactly
  k1_gtmax <<<dim3(NGT, BB), 256>>>(gt, iminfo);
  k2_main  <<<dim3(HW/256, AA, BB), 256>>>(gt, iminfo, kf0, kf1, kb0, kb1, out);
  k3_select<<<dim3(BB, 2), 1024>>>();
  k5_scatter<<<BB, 256>>>(out);
}

// round 8
// speedup vs baseline: 1.5553x; 1.1723x over previous
#include <cuda_runtime.h>
#include <stdint.h>

#define BB 32
#define NGT 20
#define FH 64
#define FW 100
#define AA 9
#define HW (FH*FW)      // 6400
#define TT (HW*AA)      // 57600
#define FG_K 128
#define RPN_BATCH_K 256
#define FULLM 0xffffffffu
#define SCAP 2048        // small-list capacity
#define T_FG (1u<<20)    // fg prune threshold on 23-bit m
#define T_BG (1u<<17)    // bg prune threshold on 23-bit m

typedef unsigned long long ull;

__device__ __constant__ float c_anchors[AA*4] = {
  -84.f,  -40.f,  99.f,  55.f,
 -176.f,  -88.f, 191.f, 103.f,
 -360.f, -184.f, 375.f, 199.f,
  -56.f,  -56.f,  71.f,  71.f,
 -120.f, -120.f, 135.f, 135.f,
 -248.f, -248.f, 263.f, 263.f,
  -36.f,  -80.f,  51.f,  95.f,
  -80.f, -168.f,  95.f, 183.f,
 -168.f, -344.f, 183.f, 359.f
};

// ---------------- Threefry-2x32 (20 rounds), matches JAX partitionable ----------------
__host__ __device__ __forceinline__ void tf2x32(uint32_t k0, uint32_t k1,
                                                uint32_t x0, uint32_t x1,
                                                uint32_t& o0, uint32_t& o1) {
  uint32_t ks2 = k0 ^ k1 ^ 0x1BD11BDAu;
  x0 += k0; x1 += k1;
#define TF_RND(r) { x0 += x1; x1 = (x1 << (r)) | (x1 >> (32 - (r))); x1 ^= x0; }
  TF_RND(13) TF_RND(15) TF_RND(26) TF_RND(6)   x0 += k1;  x1 += ks2 + 1u;
  TF_RND(17) TF_RND(29) TF_RND(16) TF_RND(24)  x0 += ks2; x1 += k0  + 2u;
  TF_RND(13) TF_RND(15) TF_RND(26) TF_RND(6)   x0 += k0;  x1 += k1  + 3u;
  TF_RND(17) TF_RND(29) TF_RND(16) TF_RND(24)  x0 += k1;  x1 += ks2 + 4u;
  TF_RND(13) TF_RND(15) TF_RND(26) TF_RND(6)   x0 += ks2; x1 += k0  + 5u;
#undef TF_RND
  o0 = x0; o1 = x1;
}

// ---------------- scratch (device globals; no allocations) ----------------
__device__ unsigned int  g_gtmax[BB*NGT];
__device__ int           g_cnt_fg[BB];
__device__ int           g_cnt_bg[BB];
__device__ int           g_cnt_sfg[BB];
__device__ int           g_cnt_sbg[BB];
__device__ int           g_nkept[BB];
__device__ int           g_kept[BB*256];        // (cls<<16) | t
__device__ ull           g_cfg[(size_t)BB*TT];  // fg full candidate keys (m<<16)|t
__device__ ull           g_cbg[(size_t)BB*TT];  // bg full candidate keys
__device__ ull           g_sfg[BB*SCAP];        // fg pruned keys (m < T_FG)
__device__ ull           g_sbg[BB*SCAP];        // bg pruned keys (m < T_BG)
__device__ float         g_uw[BB];

// ---------------- K1: gt-centric per-(b,g) max of positive inside IoUs ----------------
__global__ void k1_gtmax(const float* __restrict__ gt, const float* __restrict__ iminfo) {
  int g = blockIdx.x, b = blockIdx.y, tid = threadIdx.x;
  if (g == 0 && tid == 0) {
    g_cnt_fg[b] = 0; g_cnt_bg[b] = 0; g_nkept[b] = 0;
    g_cnt_sfg[b] = 0; g_cnt_sbg[b] = 0;
  }
  __shared__ unsigned s_best[8];
  float gx1 = __ldg(&gt[(b*NGT+g)*5+0]);
  float gy1 = __ldg(&gt[(b*NGT+g)*5+1]);
  float gx2 = __ldg(&gt[(b*NGT+g)*5+2]);
  float gy2 = __ldg(&gt[(b*NGT+g)*5+3]);
  float gw = __fadd_rn(__fsub_rn(gx2, gx1), 1.0f);
  float gh = __fadd_rn(__fsub_rn(gy2, gy1), 1.0f);
  if (gw == 1.0f && gh == 1.0f) {              // zero gt
    if (tid == 0) g_gtmax[b*NGT + g] = 0u;
    return;
  }
  float ga = __fmul_rn(gw, gh);
  float img_h = iminfo[0], img_w = iminfo[1];
  unsigned best = 0u;
  for (int a = 0; a < AA; a++) {
    float ax1_0 = c_anchors[a*4+0], ay1_0 = c_anchors[a*4+1];
    float ax2_0 = c_anchors[a*4+2], ay2_0 = c_anchors[a*4+3];
    int w0 = max(max((int)ceilf(-ax1_0 * 0.0625f),
                     (int)floorf((gx1 - ax2_0) * 0.0625f) - 1), 0);
    int w1 = min(min((int)floorf((img_w - 1.0f - ax2_0) * 0.0625f),
                     (int)ceilf((gx2 - ax1_0) * 0.0625f) + 1), FW-1);
    int h0 = max(max((int)ceilf(-ay1_0 * 0.0625f),
                     (int)floorf((gy1 - ay2_0) * 0.0625f) - 1), 0);
    int h1 = min(min((int)floorf((img_h - 1.0f - ay2_0) * 0.0625f),
                     (int)ceilf((gy2 - ay1_0) * 0.0625f) + 1), FH-1);
    if (w1 < w0 || h1 < h0) continue;
    int nw = w1 - w0 + 1, cnt = nw * (h1 - h0 + 1);
    float aw = __fadd_rn(__fsub_rn(ax2_0, ax1_0), 1.0f);
    float ah = __fadd_rn(__fsub_rn(ay2_0, ay1_0), 1.0f);
    float area = __fmul_rn(aw, ah);
    for (int i = tid; i < cnt; i += 256) {
      int w = w0 + i % nw, h = h0 + i / nw;
      float sx = 16.f * (float)w, sy = 16.f * (float)h;
      float ax1 = ax1_0 + sx, ax2 = ax2_0 + sx;
      float ay1 = ay1_0 + sy, ay2 = ay2_0 + sy;
      float iw = __fadd_rn(__fsub_rn(fminf(ax2, gx2), fmaxf(ax1, gx1)), 1.0f);
      float ih = __fadd_rn(__fsub_rn(fminf(ay2, gy2), fmaxf(ay1, gy1)), 1.0f);
      float inter = __fmul_rn(fmaxf(iw, 0.0f), fmaxf(ih, 0.0f));
      if (inter > 0.0f) {
        float ua = __fsub_rn(__fadd_rn(area, ga), inter);
        float v  = __fdiv_rn(inter, ua);
        unsigned fu = __float_as_uint(v) | 0x80000000u;
        best = max(best, fu);
      }
    }
  }
  best = __reduce_max_sync(FULLM, best);
  if ((tid & 31) == 0) s_best[tid >> 5] = best;
  __syncthreads();
  if (tid == 0) {
    unsigned m = 0u;
#pragma unroll
    for (int i = 0; i < 8; i++) m = max(m, s_best[i]);
    g_gtmax[b*NGT + g] = m;
  }
}

// ---------------- K2: full output fill + targets, labels, RNG, compaction ----------------
__global__ void k2_main(const float* __restrict__ gt, const float* __restrict__ iminfo,
                        uint32_t kf0, uint32_t kf1, uint32_t kb0, uint32_t kb1,
                        float* __restrict__ out) {
  __shared__ float s_gx1[NGT], s_gy1[NGT], s_gx2[NGT], s_gy2[NGT];
  __shared__ float s_ga[NGT], s_gcx[NGT], s_gcy[NGT], s_lw[NGT], s_lh[NGT], s_gm[NGT];
  __shared__ int s_gl[NGT];
  __shared__ int s_ng;
  int b = blockIdx.z, a = blockIdx.y, tid = threadIdx.x;
  int hw = blockIdx.x * 256 + tid;

  float ax1_0 = c_anchors[a*4+0], ay1_0 = c_anchors[a*4+1];
  float ax2_0 = c_anchors[a*4+2], ay2_0 = c_anchors[a*4+3];
  float ew = __fadd_rn(__fsub_rn(ax2_0, ax1_0), 1.0f);
  float eh = __fadd_rn(__fsub_rn(ay2_0, ay1_0), 1.0f);
  float area = __fmul_rn(ew, eh);

  if (tid < 32) {
    bool nz = false;
    if (tid < NGT) {
      float x1 = gt[(b*NGT+tid)*5+0], y1 = gt[(b*NGT+tid)*5+1];
      float x2 = gt[(b*NGT+tid)*5+2], y2 = gt[(b*NGT+tid)*5+3];
      float gw = __fadd_rn(__fsub_rn(x2, x1), 1.0f);
      float gh = __fadd_rn(__fsub_rn(y2, y1), 1.0f);
      nz = !(gw == 1.0f && gh == 1.0f);
      s_gx1[tid] = x1; s_gy1[tid] = y1; s_gx2[tid] = x2; s_gy2[tid] = y2;
      s_ga[tid]  = __fmul_rn(gw, gh);
      s_gcx[tid] = x1 + 0.5f * gw;
      s_gcy[tid] = y1 + 0.5f * gh;
      s_lw[tid]  = logf(gw / ew);
      s_lh[tid]  = logf(gh / eh);
      unsigned u_ = g_gtmax[b*NGT + tid];
      s_gm[tid]  = u_ ? __uint_as_float(u_ ^ 0x80000000u) : -999.0f;
    }
    unsigned mask = __ballot_sync(FULLM, nz);
    if (tid == 0) s_ng = __popc(mask);
    if (nz) s_gl[__popc(mask & ((1u << tid) - 1u))] = tid;
  }
  __syncthreads();

  float img_h = iminfo[0], img_w = iminfo[1];
  int h = hw / FW, w = hw - h * FW;
  float sx = (float)(w * 16), sy = (float)(h * 16);
  float ax1 = ax1_0 + sx, ax2 = ax2_0 + sx;
  float ay1 = ay1_0 + sy, ay2 = ay2_0 + sy;
  bool inside = (ax1 >= 0.f) && (ay1 >= 0.f) && (ax2 < img_w) && (ay2 < img_h);

  float mx = 0.0f; int amax = 0; bool keep = false;
  if (__ballot_sync(FULLM, inside)) {
    int ng = s_ng;
    for (int gi = 0; gi < ng; gi++) {
      int g = s_gl[gi];
      float iw = __fadd_rn(__fsub_rn(fminf(ax2, s_gx2[g]), fmaxf(ax1, s_gx1[g])), 1.0f);
      float ih = __fadd_rn(__fsub_rn(fminf(ay2, s_gy2[g]), fmaxf(ay1, s_gy1[g])), 1.0f);
      float inter = __fmul_rn(fmaxf(iw, 0.0f), fmaxf(ih, 0.0f));
      bool need = inside && (inter > 0.0f);
      float v = 0.0f;
      if (__ballot_sync(FULLM, need)) {
        if (need) {
          float ua = __fsub_rn(__fadd_rn(area, s_ga[g]), inter);
          v = __fdiv_rn(inter, ua);
        }
      }
      keep = keep || (v == s_gm[g]);
      if (v > mx) { mx = v; amax = g; }   // first-occurrence argmax
    }
  }

  int L = 2;
  if (inside) L = (keep || mx >= 0.7f) ? 1 : ((mx < 0.3f) ? 0 : 2);

  float4 tg = make_float4(0.f, 0.f, 0.f, 0.f);
  if (inside) {
    float ecx = ax1 + 0.5f * ew, ecy = ay1 + 0.5f * eh;
    tg.x = (s_gcx[amax] - ecx) / ew;
    tg.y = (s_gcy[amax] - ecy) / eh;
    tg.z = s_lw[amax];
    tg.w = s_lh[amax];
  }

  // ---- write all output planes for this (b,a,hw): label, targets, zero weights ----
  const size_t OFF1 = (size_t)BB * AA * HW;
  const size_t PL   = (size_t)BB * 36 * HW;
  size_t cb = ((size_t)b * 36 + a * 4) * HW + hw;
  out[((size_t)b * AA + a) * HW + hw] = -1.0f;          // label fill (k5 overwrites kept)
  float* tgt_o  = out + OFF1;
  float* inw_o  = out + OFF1 + PL;
  float* outw_o = out + OFF1 + 2 * PL;
  tgt_o[cb        ] = tg.x;
  tgt_o[cb +   HW ] = tg.y;
  tgt_o[cb + 2*HW ] = tg.z;
  tgt_o[cb + 3*HW ] = tg.w;
#pragma unroll
  for (int c = 0; c < 4; c++) inw_o [cb + (size_t)c * HW] = 0.0f;
#pragma unroll
  for (int c = 0; c < 4; c++) outw_o[cb + (size_t)c * HW] = 0.0f;

  // ---- RNG draw + warp-aggregated compaction ----
  unsigned ballot_fg = __ballot_sync(FULLM, L == 1);
  unsigned ballot_bg = __ballot_sync(FULLM, L == 0);
  ull key = 0ull;
  unsigned m = 0u;
  int t = hw * 9 + a;
  if (L <= 1) {
    uint32_t key0 = L ? kf0 : kb0, key1 = L ? kf1 : kb1;
    uint32_t o0, o1;
    uint32_t cntc = (uint32_t)(b * TT + t);
    tf2x32(key0, key1, 0u, cntc, o0, o1);
    m = (o0 ^ o1) >> 9;
    key = ((ull)m << 16) | (unsigned)t;
  }
  int lane = tid & 31;
  if (L == 1) {
    unsigned mask = ballot_fg;
    int leader = __ffs(mask) - 1;
    int base = 0;
    if (lane == leader) base = atomicAdd(&g_cnt_fg[b], __popc(mask));
    base = __shfl_sync(mask, base, leader);
    g_cfg[(size_t)b * TT + base + __popc(mask & ((1u << lane) - 1u))] = key;
  } else if (L == 0) {
    unsigned mask = ballot_bg;
    int leader = __ffs(mask) - 1;
    int base = 0;
    if (lane == leader) base = atomicAdd(&g_cnt_bg[b], __popc(mask));
    base = __shfl_sync(mask, base, leader);
    g_cbg[(size_t)b * TT + base + __popc(mask & ((1u << lane) - 1u))] = key;
  }
  // pruned small lists
  bool smf = (L == 1) && (m < T_FG);
  bool smb = (L == 0) && (m < T_BG);
  unsigned maskf = __ballot_sync(FULLM, smf);
  if (smf) {
    int leader = __ffs(maskf) - 1;
    int base = 0;
    if (lane == leader) base = atomicAdd(&g_cnt_sfg[b], __popc(maskf));
    base = __shfl_sync(maskf, base, leader);
    int idx = base + __popc(maskf & ((1u << lane) - 1u));
    if (idx < SCAP) g_sfg[b*SCAP + idx] = key;
  }
  unsigned maskb = __ballot_sync(FULLM, smb);
  if (smb) {
    int leader = __ffs(maskb) - 1;
    int base = 0;
    if (lane == leader) base = atomicAdd(&g_cnt_sbg[b], __popc(maskb));
    base = __shfl_sync(maskb, base, leader);
    int idx = base + __popc(maskb & ((1u << lane) - 1u));
    if (idx < SCAP) g_sbg[b*SCAP + idx] = key;
  }
}

// ---------------- K3: exact k-smallest -> kept list ----------------
__device__ __forceinline__ int blockInclScan(int local, int* s_wsum) {
  int lane = threadIdx.x & 31, wid = threadIdx.x >> 5;
  int v = local;
#pragma unroll
  for (int o = 1; o < 32; o <<= 1) { int n = __shfl_up_sync(FULLM, v, o); if (lane >= o) v += n; }
  if (lane == 31) s_wsum[wid] = v;
  __syncthreads();
  if (wid == 0) {
    int wv = s_wsum[lane];
#pragma unroll
    for (int o = 1; o < 32; o <<= 1) { int n = __shfl_up_sync(FULLM, wv, o); if (lane >= o) wv += n; }
    s_wsum[lane] = wv;
  }
  __syncthreads();
  return v + (wid ? s_wsum[wid-1] : 0);
}

__device__ __forceinline__ void emit_kept(int b, int cls, ull key) {
  int j = atomicAdd(&g_nkept[b], 1);
  g_kept[b*256 + j] = (int)(key & 0xFFFFull) | (cls << 16);
}

__global__ void __launch_bounds__(1024) k3_select() {
  __shared__ unsigned s_hist[8192];   // fallback hist; shared-path: 2048 keys + 4096 bins
  __shared__ int s_wsum[32];
  __shared__ int s_sel[2];
  __shared__ int s_cnt;
  int b = blockIdx.x, cls = blockIdx.y, tid = threadIdx.x;

  int nfg = g_cnt_fg[b];
  int n   = cls ? nfg : g_cnt_bg[b];
  int kept_fg = min(nfg, FG_K);
  int k = cls ? FG_K : (RPN_BATCH_K - kept_fg);
  if (cls == 0 && tid == 0)
    g_uw[b] = 1.0f / (float)(kept_fg + min(n, k));
  const ull* keys = (cls ? g_cfg : g_cbg) + (size_t)b * TT;

  if (n <= k) {                      // keep everything
    for (int i = tid; i < n; i += 1024) emit_kept(b, cls, keys[i]);
    return;
  }

  // ---- fast shared-memory path ----
  int ns = cls ? g_cnt_sfg[b] : g_cnt_sbg[b];
  const ull* src = nullptr; int nm = 0;
  if (n <= SCAP)                        { src = keys; nm = n; }
  else if (ns >= k && ns <= SCAP)       { src = (cls ? g_sfg : g_sbg) + b*SCAP; nm = ns; }
  if (src) {
    ull* sk = reinterpret_cast<ull*>(s_hist);       // 2048 * 8B
    unsigned* h4 = s_hist + 4096;                   // 4096 bins
    for (int i = tid; i < nm; i += 1024) sk[i] = src[i];
    for (int i = tid; i < 4096; i += 1024) h4[i] = 0u;
    __syncthreads();
    for (int i = tid; i < nm; i += 1024)
      atomicAdd(&h4[(unsigned)(sk[i] >> 27)], 1u);  // top 12 bits of m
    __syncthreads();
    int base = tid * 4, local = 0;
#pragma unroll
    for (int j = 0; j < 4; j++) local += (int)h4[base + j];
    int incl = blockInclScan(local, s_wsum);
    int excl = incl - local;
    if (k > excl && k <= incl) {
      int c = excl;
      for (int j = 0; j < 4; j++) {
        int hh = (int)h4[base + j];
        if (c + hh >= k) { s_sel[0] = base + j; s_sel[1] = c; break; }
        c += hh;
      }
    }
    __syncthreads();
    int selbin = s_sel[0], cum = s_sel[1];
    for (int i = tid; i < nm; i += 1024) {
      ull key = sk[i];
      int bin = (int)(key >> 27);
      if (bin < selbin) {
        emit_kept(b, cls, key);
      } else if (bin == selbin) {
        int lr = 0;                                  // local rank within bin
        for (int j = 0; j < nm; j++) {
          ull kj = sk[j];
          lr += ((int)(kj >> 27) == selbin) && (kj < key);
        }
        if (cum + lr < k) emit_kept(b, cls, key);
      }
    }
    return;
  }

  // ---- fallback: global multi-level radix select (rare) ----
  ull* s_keys = reinterpret_cast<ull*>(s_hist);      // overlay after hist use, cap 4096
  ull prefix = 0ull;
  int kk = k, shift = 26;
  for (int lvl = 0; ; lvl++) {
    shift = 26 - 13 * lvl;
    for (int i = tid; i < 8192; i += 1024) s_hist[i] = 0u;
    __syncthreads();
    for (int i = tid; i < n; i += 1024) {
      ull key = keys[i];
      if (lvl == 0 || (key >> (shift + 13)) == prefix)
        atomicAdd(&s_hist[(unsigned)(key >> shift) & 8191u], 1u);
    }
    __syncthreads();
    {
      int base = tid * 8, local = 0;
#pragma unroll
      for (int j = 0; j < 8; j++) local += (int)s_hist[base + j];
      int incl = blockInclScan(local, s_wsum);
      int excl = incl - local;
      if (kk > excl && kk <= incl) {
        int c = excl;
        for (int j = 0; j < 8; j++) {
          int hh = (int)s_hist[base + j];
          if (c + hh >= kk) { s_sel[0] = base + j; s_sel[1] = c; break; }
          c += hh;
        }
      }
      __syncthreads();
    }
    prefix = (prefix << 13) | (unsigned)s_sel[0];
    kk -= s_sel[1];
    int bc = (int)s_hist[s_sel[0]];
    __syncthreads();
    if (bc <= 4096 || shift == 0) break;
  }
  if (tid == 0) s_cnt = 0;
  __syncthreads();
  for (int i = tid; i < n; i += 1024) {
    ull key = keys[i];
    ull hi = key >> shift;
    if (hi < prefix) emit_kept(b, cls, key);
    else if (hi == prefix) {
      int j = atomicAdd(&s_cnt, 1);
      s_keys[j] = key;
    }
  }
  __syncthreads();
  int cnt = s_cnt;
  for (int jj = tid; jj < cnt; jj += 1024) {
    ull kj = s_keys[jj];
    int r = 0;
    for (int i = 0; i < cnt; i++) r += (s_keys[i] < kj);
    if (r < kk) emit_kept(b, cls, kj);
  }
}

// ---------------- K5: scatter kept anchors into output ----------------
__global__ void k5_scatter(float* __restrict__ out) {
  int b = blockIdx.x, tid = threadIdx.x;
  int nk = g_nkept[b];
  float u = g_uw[b];
  const size_t OFF1 = (size_t)BB * AA * HW;
  const size_t PL   = (size_t)BB * 36 * HW;
  float* inw_o  = out + OFF1 + PL;
  float* outw_o = out + OFF1 + 2 * PL;
  for (int i = tid; i < nk; i += 256) {
    int e = g_kept[b*256 + i];
    int t = e & 0xFFFF, cls = e >> 16;
    int a = t % 9, hw = t / 9;
    out[((size_t)b * AA + a) * HW + hw] = (float)cls;
    size_t cb = ((size_t)b * 36 + a * 4) * HW + hw;
    if (cls) {
#pragma unroll
      for (int c = 0; c < 4; c++) inw_o[cb + (size_t)c * HW] = 1.0f;
    }
#pragma unroll
    for (int c = 0; c < 4; c++) outw_o[cb + (size_t)c * HW] = u;
  }
}

// ---------------- host ----------------
extern "C" void kernel_launch(void* const* d_in, const int* in_sizes, int n_in,
                              void* d_out, int out_size) {
  const float* gt     = (const float*)d_in[1];   // gt_boxes [32,20,5]
  const float* iminfo = (const float*)d_in[2];   // im_info [32,3]
  float* out = (float*)d_out;

  uint32_t kf0, kf1, kb0, kb1;
  tf2x32(0u, 42u, 0u, 0u, kf0, kf1);
  tf2x32(0u, 42u, 0u, 1u, kb0, kb1);

  k1_gtmax <<<dim3(NGT, BB), 256>>>(gt, iminfo);
  k2_main  <<<dim3(HW/256, AA, BB), 256>>>(gt, iminfo, kf0, kf1, kb0, kb1, out);
  k3_select<<<dim3(BB, 2), 1024>>>();
  k5_scatter<<<BB, 256>>>(out);
}

// round 9
// speedup vs baseline: 1.6876x; 1.0851x over previous
#include <cuda_runtime.h>
#include <stdint.h>

#define BB 32
#define NGT 20
#define FH 64
#define FW 100
#define AA 9
#define HW (FH*FW)      // 6400
#define TT (HW*AA)      // 57600
#define FG_K 128
#define RPN_BATCH_K 256
#define FULLM 0xffffffffu
#define SCAP 2048        // small-list capacity
#define T_FG (1u<<20)    // fg prune threshold on 23-bit m
#define T_BG (1u<<17)    // bg prune threshold on 23-bit m

typedef unsigned long long ull;

__device__ __constant__ float c_anchors[AA*4] = {
  -84.f,  -40.f,  99.f,  55.f,
 -176.f,  -88.f, 191.f, 103.f,
 -360.f, -184.f, 375.f, 199.f,
  -56.f,  -56.f,  71.f,  71.f,
 -120.f, -120.f, 135.f, 135.f,
 -248.f, -248.f, 263.f, 263.f,
  -36.f,  -80.f,  51.f,  95.f,
  -80.f, -168.f,  95.f, 183.f,
 -168.f, -344.f, 183.f, 359.f
};

// ---------------- Threefry-2x32 (20 rounds), matches JAX partitionable ----------------
__host__ __device__ __forceinline__ void tf2x32(uint32_t k0, uint32_t k1,
                                                uint32_t x0, uint32_t x1,
                                                uint32_t& o0, uint32_t& o1) {
  uint32_t ks2 = k0 ^ k1 ^ 0x1BD11BDAu;
  x0 += k0; x1 += k1;
#define TF_RND(r) { x0 += x1; x1 = (x1 << (r)) | (x1 >> (32 - (r))); x1 ^= x0; }
  TF_RND(13) TF_RND(15) TF_RND(26) TF_RND(6)   x0 += k1;  x1 += ks2 + 1u;
  TF_RND(17) TF_RND(29) TF_RND(16) TF_RND(24)  x0 += ks2; x1 += k0  + 2u;
  TF_RND(13) TF_RND(15) TF_RND(26) TF_RND(6)   x0 += k0;  x1 += k1  + 3u;
  TF_RND(17) TF_RND(29) TF_RND(16) TF_RND(24)  x0 += k1;  x1 += ks2 + 4u;
  TF_RND(13) TF_RND(15) TF_RND(26) TF_RND(6)   x0 += ks2; x1 += k0  + 5u;
#undef TF_RND
  o0 = x0; o1 = x1;
}

// ---------------- scratch (device globals; no allocations) ----------------
__device__ unsigned int  g_gtmax[BB*NGT];
__device__ int           g_cnt_fg[BB];
__device__ int           g_cnt_bg[BB];
__device__ int           g_cnt_sfg[BB];
__device__ int           g_cnt_sbg[BB];
__device__ ull           g_cfg[(size_t)BB*TT];  // fg full candidate keys (m<<16)|t
__device__ ull           g_cbg[(size_t)BB*TT];  // bg full candidate keys
__device__ ull           g_sfg[BB*SCAP];        // fg pruned keys (m < T_FG)
__device__ ull           g_sbg[BB*SCAP];        // bg pruned keys (m < T_BG)

// ---------------- K1: gt-centric per-(b,g) max of positive inside IoUs ----------------
__global__ void k1_gtmax(const float* __restrict__ gt, const float* __restrict__ iminfo) {
  int g = blockIdx.x, b = blockIdx.y, tid = threadIdx.x;
  if (g == 0 && tid == 0) {
    g_cnt_fg[b] = 0; g_cnt_bg[b] = 0;
    g_cnt_sfg[b] = 0; g_cnt_sbg[b] = 0;
  }
  __shared__ unsigned s_best[8];
  float gx1 = __ldg(&gt[(b*NGT+g)*5+0]);
  float gy1 = __ldg(&gt[(b*NGT+g)*5+1]);
  float gx2 = __ldg(&gt[(b*NGT+g)*5+2]);
  float gy2 = __ldg(&gt[(b*NGT+g)*5+3]);
  float gw = __fadd_rn(__fsub_rn(gx2, gx1), 1.0f);
  float gh = __fadd_rn(__fsub_rn(gy2, gy1), 1.0f);
  if (gw == 1.0f && gh == 1.0f) {              // zero gt
    if (tid == 0) g_gtmax[b*NGT + g] = 0u;
    return;
  }
  float ga = __fmul_rn(gw, gh);
  float img_h = iminfo[0], img_w = iminfo[1];
  unsigned best = 0u;
  for (int a = 0; a < AA; a++) {
    float ax1_0 = c_anchors[a*4+0], ay1_0 = c_anchors[a*4+1];
    float ax2_0 = c_anchors[a*4+2], ay2_0 = c_anchors[a*4+3];
    int w0 = max(max((int)ceilf(-ax1_0 * 0.0625f),
                     (int)floorf((gx1 - ax2_0) * 0.0625f) - 1), 0);
    int w1 = min(min((int)floorf((img_w - 1.0f - ax2_0) * 0.0625f),
                     (int)ceilf((gx2 - ax1_0) * 0.0625f) + 1), FW-1);
    int h0 = max(max((int)ceilf(-ay1_0 * 0.0625f),
                     (int)floorf((gy1 - ay2_0) * 0.0625f) - 1), 0);
    int h1 = min(min((int)floorf((img_h - 1.0f - ay2_0) * 0.0625f),
                     (int)ceilf((gy2 - ay1_0) * 0.0625f) + 1), FH-1);
    if (w1 < w0 || h1 < h0) continue;
    int nw = w1 - w0 + 1, cnt = nw * (h1 - h0 + 1);
    float aw = __fadd_rn(__fsub_rn(ax2_0, ax1_0), 1.0f);
    float ah = __fadd_rn(__fsub_rn(ay2_0, ay1_0), 1.0f);
    float area = __fmul_rn(aw, ah);
    for (int i = tid; i < cnt; i += 256) {
      int w = w0 + i % nw, h = h0 + i / nw;
      float sx = 16.f * (float)w, sy = 16.f * (float)h;
      float ax1 = ax1_0 + sx, ax2 = ax2_0 + sx;
      float ay1 = ay1_0 + sy, ay2 = ay2_0 + sy;
      float iw = __fadd_rn(__fsub_rn(fminf(ax2, gx2), fmaxf(ax1, gx1)), 1.0f);
      float ih = __fadd_rn(__fsub_rn(fminf(ay2, gy2), fmaxf(ay1, gy1)), 1.0f);
      float inter = __fmul_rn(fmaxf(iw, 0.0f), fmaxf(ih, 0.0f));
      if (inter > 0.0f) {
        float ua = __fsub_rn(__fadd_rn(area, ga), inter);
        float v  = __fdiv_rn(inter, ua);
        unsigned fu = __float_as_uint(v) | 0x80000000u;
        best = max(best, fu);
      }
    }
  }
  best = __reduce_max_sync(FULLM, best);
  if ((tid & 31) == 0) s_best[tid >> 5] = best;
  __syncthreads();
  if (tid == 0) {
    unsigned m = 0u;
#pragma unroll
    for (int i = 0; i < 8; i++) m = max(m, s_best[i]);
    g_gtmax[b*NGT + g] = m;
  }
}

// warp-aggregated allocation: returns base index for this thread's cnt items
__device__ __forceinline__ int warp_alloc(int* ctr, int cnt) {
  int lane = threadIdx.x & 31;
  int v = cnt;
#pragma unroll
  for (int o = 1; o < 32; o <<= 1) {
    int n = __shfl_up_sync(FULLM, v, o);
    if (lane >= o) v += n;
  }
  int total = __shfl_sync(FULLM, v, 31);
  int base = 0;
  if (lane == 31 && total) base = atomicAdd(ctr, total);
  base = __shfl_sync(FULLM, base, 31);
  return base + v - cnt;
}

// ---------------- K2: 4-wide: fill+targets+labels+RNG+compaction ----------------
__global__ void __launch_bounds__(320) k2_main(
    const float* __restrict__ gt, const float* __restrict__ iminfo,
    uint32_t kf0, uint32_t kf1, uint32_t kb0, uint32_t kb1,
    float* __restrict__ out) {
  __shared__ float s_gx1[NGT], s_gy1[NGT], s_gx2[NGT], s_gy2[NGT];
  __shared__ float s_ga[NGT], s_gcx[NGT], s_gcy[NGT], s_lw[NGT], s_lh[NGT], s_gm[NGT];
  __shared__ int s_gl[NGT];
  __shared__ int s_ng;
  int b = blockIdx.z, a = blockIdx.y, tid = threadIdx.x;
  int hw0 = (blockIdx.x * 320 + tid) * 4;       // groups of 4 never cross a row (100%4==0)

  float ax1_0 = c_anchors[a*4+0], ay1_0 = c_anchors[a*4+1];
  float ax2_0 = c_anchors[a*4+2], ay2_0 = c_anchors[a*4+3];
  float ew = __fadd_rn(__fsub_rn(ax2_0, ax1_0), 1.0f);
  float eh = __fadd_rn(__fsub_rn(ay2_0, ay1_0), 1.0f);
  float area = __fmul_rn(ew, eh);

  if (tid < 32) {
    bool nz = false;
    if (tid < NGT) {
      float x1 = gt[(b*NGT+tid)*5+0], y1 = gt[(b*NGT+tid)*5+1];
      float x2 = gt[(b*NGT+tid)*5+2], y2 = gt[(b*NGT+tid)*5+3];
      float gw = __fadd_rn(__fsub_rn(x2, x1), 1.0f);
      float gh = __fadd_rn(__fsub_rn(y2, y1), 1.0f);
      nz = !(gw == 1.0f && gh == 1.0f);
      s_gx1[tid] = x1; s_gy1[tid] = y1; s_gx2[tid] = x2; s_gy2[tid] = y2;
      s_ga[tid]  = __fmul_rn(gw, gh);
      s_gcx[tid] = x1 + 0.5f * gw;
      s_gcy[tid] = y1 + 0.5f * gh;
      s_lw[tid]  = logf(gw / ew);
      s_lh[tid]  = logf(gh / eh);
      unsigned u_ = g_gtmax[b*NGT + tid];
      s_gm[tid]  = u_ ? __uint_as_float(u_ ^ 0x80000000u) : -999.0f;
    }
    unsigned mask = __ballot_sync(FULLM, nz);
    if (tid == 0) s_ng = __popc(mask);
    if (nz) s_gl[__popc(mask & ((1u << tid) - 1u))] = tid;
  }
  __syncthreads();

  float img_h = iminfo[0], img_w = iminfo[1];
  int h = hw0 / FW, w0 = hw0 - h * FW;
  float sy = 16.f * (float)h;
  float ay1 = ay1_0 + sy, ay2 = ay2_0 + sy;
  bool iny = (ay1 >= 0.f) && (ay2 < img_h);

  float ax1[4], ax2v[4];
  bool inside[4];
  float mx[4] = {0.f, 0.f, 0.f, 0.f};
  int amax[4] = {0, 0, 0, 0};
  bool keep[4] = {false, false, false, false};
#pragma unroll
  for (int p = 0; p < 4; p++) {
    float sx = 16.f * (float)(w0 + p);
    ax1[p]  = ax1_0 + sx;
    ax2v[p] = ax2_0 + sx;
    inside[p] = iny && (ax1[p] >= 0.f) && (ax2v[p] < img_w);
  }

  int ng = s_ng;
  if (inside[0] || inside[3]) {     // inside is monotone-interval in w; covers 1,2
    for (int gi = 0; gi < ng; gi++) {
      int g = s_gl[gi];
      float gx1 = s_gx1[g], gx2 = s_gx2[g], ga = s_ga[g], gm = s_gm[g];
      float ihh = __fadd_rn(__fsub_rn(fminf(ay2, s_gy2[g]), fmaxf(ay1, s_gy1[g])), 1.0f);
      ihh = fmaxf(ihh, 0.0f);
#pragma unroll
      for (int p = 0; p < 4; p++) {
        float iw = __fadd_rn(__fsub_rn(fminf(ax2v[p], gx2), fmaxf(ax1[p], gx1)), 1.0f);
        float inter = __fmul_rn(fmaxf(iw, 0.0f), ihh);
        float v = 0.0f;
        if (inside[p] && inter > 0.0f) {
          float ua = __fsub_rn(__fadd_rn(area, ga), inter);
          v = __fdiv_rn(inter, ua);
        }
        keep[p] = keep[p] || (v == gm);
        if (v > mx[p]) { mx[p] = v; amax[p] = g; }
      }
    }
  }

  int L[4];
  float4 tgp[4];
#pragma unroll
  for (int p = 0; p < 4; p++) {
    L[p] = 2;
    if (inside[p]) L[p] = (keep[p] || mx[p] >= 0.7f) ? 1 : ((mx[p] < 0.3f) ? 0 : 2);
    tgp[p] = make_float4(0.f, 0.f, 0.f, 0.f);
    if (inside[p]) {
      int am = amax[p];
      float ecx = ax1[p] + 0.5f * ew, ecy = ay1 + 0.5f * eh;
      tgp[p].x = (s_gcx[am] - ecx) / ew;
      tgp[p].y = (s_gcy[am] - ecy) / eh;
      tgp[p].z = s_lw[am];
      tgp[p].w = s_lh[am];
    }
  }

  // ---- vector stores: label fill, 4 target planes, 8 zero weight planes ----
  const size_t OFF1 = (size_t)BB * AA * HW;
  const size_t PL   = (size_t)BB * 36 * HW;
  size_t cb = ((size_t)b * 36 + a * 4) * HW + hw0;
  float4 z4 = make_float4(0.f, 0.f, 0.f, 0.f);
  *reinterpret_cast<float4*>(&out[((size_t)b * AA + a) * HW + hw0]) =
      make_float4(-1.f, -1.f, -1.f, -1.f);
  float* tgt_o  = out + OFF1;
  float* inw_o  = out + OFF1 + PL;
  float* outw_o = out + OFF1 + 2 * PL;
  *reinterpret_cast<float4*>(&tgt_o[cb        ]) = make_float4(tgp[0].x, tgp[1].x, tgp[2].x, tgp[3].x);
  *reinterpret_cast<float4*>(&tgt_o[cb +   HW ]) = make_float4(tgp[0].y, tgp[1].y, tgp[2].y, tgp[3].y);
  *reinterpret_cast<float4*>(&tgt_o[cb + 2*HW ]) = make_float4(tgp[0].z, tgp[1].z, tgp[2].z, tgp[3].z);
  *reinterpret_cast<float4*>(&tgt_o[cb + 3*HW ]) = make_float4(tgp[0].w, tgp[1].w, tgp[2].w, tgp[3].w);
#pragma unroll
  for (int c = 0; c < 4; c++) *reinterpret_cast<float4*>(&inw_o [cb + (size_t)c * HW]) = z4;
#pragma unroll
  for (int c = 0; c < 4; c++) *reinterpret_cast<float4*>(&outw_o[cb + (size_t)c * HW]) = z4;

  // ---- RNG draws ----
  ull key[4];
  unsigned m[4];
  int cf = 0, cbg = 0, csf = 0, csb = 0;
#pragma unroll
  for (int p = 0; p < 4; p++) {
    m[p] = 0u; key[p] = 0ull;
    if (L[p] <= 1) {
      int t = (hw0 + p) * 9 + a;
      uint32_t key0 = L[p] ? kf0 : kb0, key1 = L[p] ? kf1 : kb1;
      uint32_t o0, o1;
      tf2x32(key0, key1, 0u, (uint32_t)(b * TT + t), o0, o1);
      m[p] = (o0 ^ o1) >> 9;
      key[p] = ((ull)m[p] << 16) | (unsigned)t;
      if (L[p] == 1) { cf++; if (m[p] < T_FG) csf++; }
      else           { cbg++; if (m[p] < T_BG) csb++; }
    }
  }

  // ---- warp-aggregated compaction ----
  int basef  = warp_alloc(&g_cnt_fg[b],  cf);
  int baseb  = warp_alloc(&g_cnt_bg[b],  cbg);
  int basesf = warp_alloc(&g_cnt_sfg[b], csf);
  int basesb = warp_alloc(&g_cnt_sbg[b], csb);
#pragma unroll
  for (int p = 0; p < 4; p++) {
    if (L[p] == 1) {
      g_cfg[(size_t)b * TT + basef++] = key[p];
      if (m[p] < T_FG) { if (basesf < SCAP) g_sfg[b*SCAP + basesf] = key[p]; basesf++; }
    } else if (L[p] == 0) {
      g_cbg[(size_t)b * TT + baseb++] = key[p];
      if (m[p] < T_BG) { if (basesb < SCAP) g_sbg[b*SCAP + basesb] = key[p]; basesb++; }
    }
  }
}

// ---------------- K3: exact k-smallest -> direct output scatter ----------------
__device__ __forceinline__ int blockInclScan(int local, int* s_wsum) {
  int lane = threadIdx.x & 31, wid = threadIdx.x >> 5;
  int v = local;
#pragma unroll
  for (int o = 1; o < 32; o <<= 1) { int n = __shfl_up_sync(FULLM, v, o); if (lane >= o) v += n; }
  if (lane == 31) s_wsum[wid] = v;
  __syncthreads();
  if (wid == 0) {
    int wv = s_wsum[lane];
#pragma unroll
    for (int o = 1; o < 32; o <<= 1) { int n = __shfl_up_sync(FULLM, wv, o); if (lane >= o) wv += n; }
    s_wsum[lane] = wv;
  }
  __syncthreads();
  return v + (wid ? s_wsum[wid-1] : 0);
}

__device__ __forceinline__ void scatter_keep(float* out, int b, int cls, float u, ull key) {
  const size_t OFF1 = (size_t)BB * AA * HW;
  const size_t PL   = (size_t)BB * 36 * HW;
  int t = (int)(key & 0xFFFFull);
  int a = t % 9, hw = t / 9;
  out[((size_t)b * AA + a) * HW + hw] = (float)cls;
  size_t cb = ((size_t)b * 36 + a * 4) * HW + hw;
  float* inw_o  = out + OFF1 + PL;
  float* outw_o = out + OFF1 + 2 * PL;
  if (cls) {
#pragma unroll
    for (int c = 0; c < 4; c++) inw_o[cb + (size_t)c * HW] = 1.0f;
  }
#pragma unroll
  for (int c = 0; c < 4; c++) outw_o[cb + (size_t)c * HW] = u;
}

__global__ void __launch_bounds__(1024) k3_select(float* __restrict__ out) {
  __shared__ unsigned s_hist[8192];   // fallback hist; shared-path: 2048 keys + 4096 bins
  __shared__ int s_wsum[32];
  __shared__ int s_sel[2];
  __shared__ int s_cnt;
  int b = blockIdx.x, cls = blockIdx.y, tid = threadIdx.x;

  int nfg = g_cnt_fg[b], nbg = g_cnt_bg[b];
  int kept_fg = min(nfg, FG_K);
  int kbg = RPN_BATCH_K - kept_fg;
  float u = 1.0f / (float)(kept_fg + min(nbg, kbg));
  int n = cls ? nfg : nbg;
  int k = cls ? FG_K : kbg;
  const ull* keys = (cls ? g_cfg : g_cbg) + (size_t)b * TT;

  if (n <= k) {                      // keep everything
    for (int i = tid; i < n; i += 1024) scatter_keep(out, b, cls, u, keys[i]);
    return;
  }

  // ---- fast shared-memory path ----
  int ns = cls ? g_cnt_sfg[b] : g_cnt_sbg[b];
  const ull* src = nullptr; int nm = 0;
  if (n <= SCAP)                        { src = keys; nm = n; }
  else if (ns >= k && ns <= SCAP)       { src = (cls ? g_sfg : g_sbg) + b*SCAP; nm = ns; }
  if (src) {
    ull* sk = reinterpret_cast<ull*>(s_hist);       // 2048 * 8B
    unsigned* h4 = s_hist + 4096;                   // 4096 bins
    for (int i = tid; i < nm; i += 1024) sk[i] = src[i];
    for (int i = tid; i < 4096; i += 1024) h4[i] = 0u;
    __syncthreads();
    for (int i = tid; i < nm; i += 1024)
      atomicAdd(&h4[(unsigned)(sk[i] >> 27)], 1u);  // top 12 bits of m
    __syncthreads();
    int base = tid * 4, local = 0;
#pragma unroll
    for (int j = 0; j < 4; j++) local += (int)h4[base + j];
    int incl = blockInclScan(local, s_wsum);
    int excl = incl - local;
    if (k > excl && k <= incl) {
      int c = excl;
      for (int j = 0; j < 4; j++) {
        int hh = (int)h4[base + j];
        if (c + hh >= k) { s_sel[0] = base + j; s_sel[1] = c; break; }
        c += hh;
      }
    }
    __syncthreads();
    int selbin = s_sel[0], cum = s_sel[1];
    for (int i = tid; i < nm; i += 1024) {
      ull key = sk[i];
      int bin = (int)(key >> 27);
      if (bin < selbin) {
        scatter_keep(out, b, cls, u, key);
      } else if (bin == selbin) {
        int lr = 0;
        for (int j = 0; j < nm; j++) {
          ull kj = sk[j];
          lr += ((int)(kj >> 27) == selbin) && (kj < key);
        }
        if (cum + lr < k) scatter_keep(out, b, cls, u, key);
      }
    }
    return;
  }

  // ---- fallback: global multi-level radix select (rare) ----
  ull* s_keys = reinterpret_cast<ull*>(s_hist);
  ull prefix = 0ull;
  int kk = k, shift = 26;
  for (int lvl = 0; ; lvl++) {
    shift = 26 - 13 * lvl;
    for (int i = tid; i < 8192; i += 1024) s_hist[i] = 0u;
    __syncthreads();
    for (int i = tid; i < n; i += 1024) {
      ull key = keys[i];
      if (lvl == 0 || (key >> (shift + 13)) == prefix)
        atomicAdd(&s_hist[(unsigned)(key >> shift) & 8191u], 1u);
    }
    __syncthreads();
    {
      int base = tid * 8, local = 0;
#pragma unroll
      for (int j = 0; j < 8; j++) local += (int)s_hist[base + j];
      int incl = blockInclScan(local, s_wsum);
      int excl = incl - local;
      if (kk > excl && kk <= incl) {
        int c = excl;
        for (int j = 0; j < 8; j++) {
          int hh = (int)s_hist[base + j];
          if (c + hh >= kk) { s_sel[0] = base + j; s_sel[1] = c; break; }
          c += hh;
        }
      }
      __syncthreads();
    }
    prefix = (prefix << 13) | (unsigned)s_sel[0];
    kk -= s_sel[1];
    int bc = (int)s_hist[s_sel[0]];
    __syncthreads();
    if (bc <= 4096 || shift == 0) break;
  }
  if (tid == 0) s_cnt = 0;
  __syncthreads();
  for (int i = tid; i < n; i += 1024) {
    ull key = keys[i];
    ull hi = key >> shift;
    if (hi < prefix) scatter_keep(out, b, cls, u, key);
    else if (hi == prefix) {
      int j = atomicAdd(&s_cnt, 1);
      s_keys[j] = key;
    }
  }
  __syncthreads();
  int cnt = s_cnt;
  for (int jj = tid; jj < cnt; jj += 1024) {
    ull kj = s_keys[jj];
    int r = 0;
    for (int i = 0; i < cnt; i++) r += (s_keys[i] < kj);
    if (r < kk) scatter_keep(out, b, cls, u, kj);
  }
}

// ---------------- host ----------------
extern "C" void kernel_launch(void* const* d_in, const int* in_sizes, int n_in,
                              void* d_out, int out_size) {
  const float* gt     = (const float*)d_in[1];   // gt_boxes [32,20,5]
  const float* iminfo = (const float*)d_in[2];   // im_info [32,3]
  float* out = (float*)d_out;

  uint32_t kf0, kf1, kb0, kb1;
  tf2x32(0u, 42u, 0u, 0u, kf0, kf1);
  tf2x32(0u, 42u, 0u, 1u, kb0, kb1);

  k1_gtmax <<<dim3(NGT, BB), 256>>>(gt, iminfo);
  k2_main  <<<dim3(5, AA, BB), 320>>>(gt, iminfo, kf0, kf1, kb0, kb1, out);
  k3_select<<<dim3(BB, 2), 1024>>>(out);
}

// round 10
// speedup vs baseline: 1.7798x; 1.0546x over previous
#include <cuda_runtime.h>
#include <stdint.h>

#define BB 32
#define NGT 20
#define FH 64
#define FW 100
#define AA 9
#define HW (FH*FW)      // 6400
#define TT (HW*AA)      // 57600
#define FG_K 128
#define RPN_BATCH_K 256
#define FULLM 0xffffffffu
#define SCAP 2048        // small-list capacity
#define T_FG (1u<<20)    // fg prune threshold on 23-bit m
#define T_BG (1u<<17)    // bg prune threshold on 23-bit m

typedef unsigned long long ull;

__device__ __constant__ float c_anchors[AA*4] = {
  -84.f,  -40.f,  99.f,  55.f,
 -176.f,  -88.f, 191.f, 103.f,
 -360.f, -184.f, 375.f, 199.f,
  -56.f,  -56.f,  71.f,  71.f,
 -120.f, -120.f, 135.f, 135.f,
 -248.f, -248.f, 263.f, 263.f,
  -36.f,  -80.f,  51.f,  95.f,
  -80.f, -168.f,  95.f, 183.f,
 -168.f, -344.f, 183.f, 359.f
};

// ---------------- Threefry-2x32 (20 rounds), matches JAX partitionable ----------------
__host__ __device__ __forceinline__ void tf2x32(uint32_t k0, uint32_t k1,
                                                uint32_t x0, uint32_t x1,
                                                uint32_t& o0, uint32_t& o1) {
  uint32_t ks2 = k0 ^ k1 ^ 0x1BD11BDAu;
  x0 += k0; x1 += k1;
#define TF_RND(r) { x0 += x1; x1 = (x1 << (r)) | (x1 >> (32 - (r))); x1 ^= x0; }
  TF_RND(13) TF_RND(15) TF_RND(26) TF_RND(6)   x0 += k1;  x1 += ks2 + 1u;
  TF_RND(17) TF_RND(29) TF_RND(16) TF_RND(24)  x0 += ks2; x1 += k0  + 2u;
  TF_RND(13) TF_RND(15) TF_RND(26) TF_RND(6)   x0 += k0;  x1 += k1  + 3u;
  TF_RND(17) TF_RND(29) TF_RND(16) TF_RND(24)  x0 += k1;  x1 += ks2 + 4u;
  TF_RND(13) TF_RND(15) TF_RND(26) TF_RND(6)   x0 += ks2; x1 += k0  + 5u;
#undef TF_RND
  o0 = x0; o1 = x1;
}

// ---------------- scratch (device globals; no allocations) ----------------
__device__ unsigned int  g_gtmax[BB*NGT];
__device__ int           g_cnt_fg[BB];
__device__ int           g_cnt_bg[BB];
__device__ int           g_cnt_sfg[BB];
__device__ int           g_cnt_sbg[BB];
__device__ ull           g_cfg[(size_t)BB*TT];  // fg full candidate keys (m<<16)|t
__device__ ull           g_cbg[(size_t)BB*TT];  // bg full candidate keys
__device__ ull           g_sfg[BB*SCAP];        // fg pruned keys (m < T_FG)
__device__ ull           g_sbg[BB*SCAP];        // bg pruned keys (m < T_BG)

// ---------------- K1: gt-centric per-(b,g) max; warp-per-row, guarded div ----------------
__global__ void k1_gtmax(const float* __restrict__ gt, const float* __restrict__ iminfo) {
  int g = blockIdx.x, b = blockIdx.y, tid = threadIdx.x;
  int lane = tid & 31, wrp = tid >> 5;           // 8 warps
  if (g == 0 && tid == 0) {
    g_cnt_fg[b] = 0; g_cnt_bg[b] = 0;
    g_cnt_sfg[b] = 0; g_cnt_sbg[b] = 0;
  }
  __shared__ unsigned s_best[8];
  float gx1 = __ldg(&gt[(b*NGT+g)*5+0]);
  float gy1 = __ldg(&gt[(b*NGT+g)*5+1]);
  float gx2 = __ldg(&gt[(b*NGT+g)*5+2]);
  float gy2 = __ldg(&gt[(b*NGT+g)*5+3]);
  float gw = __fadd_rn(__fsub_rn(gx2, gx1), 1.0f);
  float gh = __fadd_rn(__fsub_rn(gy2, gy1), 1.0f);
  if (gw == 1.0f && gh == 1.0f) {              // zero gt
    if (tid == 0) g_gtmax[b*NGT + g] = 0u;
    return;
  }
  float ga = __fmul_rn(gw, gh);
  float img_h = iminfo[0], img_w = iminfo[1];
  float bestf = 0.0f;
  for (int a = 0; a < AA; a++) {
    float ax1_0 = c_anchors[a*4+0], ay1_0 = c_anchors[a*4+1];
    float ax2_0 = c_anchors[a*4+2], ay2_0 = c_anchors[a*4+3];
    int w0 = max(max((int)ceilf(-ax1_0 * 0.0625f),
                     (int)floorf((gx1 - ax2_0) * 0.0625f) - 1), 0);
    int w1 = min(min((int)floorf((img_w - 1.0f - ax2_0) * 0.0625f),
                     (int)ceilf((gx2 - ax1_0) * 0.0625f) + 1), FW-1);
    int h0 = max(max((int)ceilf(-ay1_0 * 0.0625f),
                     (int)floorf((gy1 - ay2_0) * 0.0625f) - 1), 0);
    int h1 = min(min((int)floorf((img_h - 1.0f - ay2_0) * 0.0625f),
                     (int)ceilf((gy2 - ay1_0) * 0.0625f) + 1), FH-1);
    if (w1 < w0 || h1 < h0) continue;
    float aw = __fadd_rn(__fsub_rn(ax2_0, ax1_0), 1.0f);
    float ah = __fadd_rn(__fsub_rn(ay2_0, ay1_0), 1.0f);
    float area = __fmul_rn(aw, ah);
    for (int hh = h0 + wrp; hh <= h1; hh += 8) {
      float sy = 16.f * (float)hh;
      float ay1 = ay1_0 + sy, ay2 = ay2_0 + sy;
      float ihh = __fadd_rn(__fsub_rn(fminf(ay2, gy2), fmaxf(ay1, gy1)), 1.0f);
      ihh = fmaxf(ihh, 0.0f);
      if (ihh <= 0.0f) continue;
      for (int w = w0 + lane; w <= w1; w += 32) {
        float sx = 16.f * (float)w;
        float ax1 = ax1_0 + sx, ax2 = ax2_0 + sx;
        float iw = __fadd_rn(__fsub_rn(fminf(ax2, gx2), fmaxf(ax1, gx1)), 1.0f);
        float inter = __fmul_rn(fmaxf(iw, 0.0f), ihh);
        if (inter > 0.0f) {
          float ua = __fsub_rn(__fadd_rn(area, ga), inter);
          // guarded division: only pairs that can exceed current best
          if (inter > __fmul_rn(bestf, ua) * 0.9999995f) {
            float v = __fdiv_rn(inter, ua);
            if (v > bestf) bestf = v;
          }
        }
      }
    }
  }
  unsigned fu = (bestf > 0.0f) ? (__float_as_uint(bestf) | 0x80000000u) : 0u;
  fu = __reduce_max_sync(FULLM, fu);
  if (lane == 0) s_best[wrp] = fu;
  __syncthreads();
  if (tid == 0) {
    unsigned m = 0u;
#pragma unroll
    for (int i = 0; i < 8; i++) m = max(m, s_best[i]);
    g_gtmax[b*NGT + g] = m;
  }
}

// warp-aggregated allocation: returns base index for this thread's cnt items
__device__ __forceinline__ int warp_alloc(int* ctr, int cnt) {
  int lane = threadIdx.x & 31;
  int v = cnt;
#pragma unroll
  for (int o = 1; o < 32; o <<= 1) {
    int n = __shfl_up_sync(FULLM, v, o);
    if (lane >= o) v += n;
  }
  int total = __shfl_sync(FULLM, v, 31);
  int base = 0;
  if (lane == 31 && total) base = atomicAdd(ctr, total);
  base = __shfl_sync(FULLM, base, 31);
  return base + v - cnt;
}

// ---------------- K2: 4-wide: fill+targets+labels+RNG+compaction ----------------
__global__ void __launch_bounds__(320) k2_main(
    const float* __restrict__ gt, const float* __restrict__ iminfo,
    uint32_t kf0, uint32_t kf1, uint32_t kb0, uint32_t kb1,
    float* __restrict__ out) {
  __shared__ float s_gx1[NGT], s_gy1[NGT], s_gx2[NGT], s_gy2[NGT];
  __shared__ float s_ga[NGT], s_gcx[NGT], s_gcy[NGT], s_lw[NGT], s_lh[NGT], s_gm[NGT];
  __shared__ int s_gl[NGT];
  __shared__ int s_ng;
  int b = blockIdx.z, a = blockIdx.y, tid = threadIdx.x;
  int hw0 = (blockIdx.x * 320 + tid) * 4;       // groups of 4 never cross a row (100%4==0)

  float ax1_0 = c_anchors[a*4+0], ay1_0 = c_anchors[a*4+1];
  float ax2_0 = c_anchors[a*4+2], ay2_0 = c_anchors[a*4+3];
  float ew = __fadd_rn(__fsub_rn(ax2_0, ax1_0), 1.0f);
  float eh = __fadd_rn(__fsub_rn(ay2_0, ay1_0), 1.0f);
  float area = __fmul_rn(ew, eh);

  if (tid < 32) {
    bool nz = false;
    if (tid < NGT) {
      float x1 = gt[(b*NGT+tid)*5+0], y1 = gt[(b*NGT+tid)*5+1];
      float x2 = gt[(b*NGT+tid)*5+2], y2 = gt[(b*NGT+tid)*5+3];
      float gw = __fadd_rn(__fsub_rn(x2, x1), 1.0f);
      float gh = __fadd_rn(__fsub_rn(y2, y1), 1.0f);
      nz = !(gw == 1.0f && gh == 1.0f);
      s_gx1[tid] = x1; s_gy1[tid] = y1; s_gx2[tid] = x2; s_gy2[tid] = y2;
      s_ga[tid]  = __fmul_rn(gw, gh);
      s_gcx[tid] = x1 + 0.5f * gw;
      s_gcy[tid] = y1 + 0.5f * gh;
      s_lw[tid]  = logf(gw / ew);
      s_lh[tid]  = logf(gh / eh);
      unsigned u_ = g_gtmax[b*NGT + tid];
      s_gm[tid]  = u_ ? __uint_as_float(u_ ^ 0x80000000u) : -999.0f;
    }
    unsigned mask = __ballot_sync(FULLM, nz);
    if (tid == 0) s_ng = __popc(mask);
    if (nz) s_gl[__popc(mask & ((1u << tid) - 1u))] = tid;
  }
  __syncthreads();

  float img_h = iminfo[0], img_w = iminfo[1];
  int h = hw0 / FW, w0 = hw0 - h * FW;
  float sy = 16.f * (float)h;
  float ay1 = ay1_0 + sy, ay2 = ay2_0 + sy;
  bool iny = (ay1 >= 0.f) && (ay2 < img_h);

  float ax1[4], ax2v[4];
  bool inside[4];
  float mx[4] = {0.f, 0.f, 0.f, 0.f};
  int amax[4] = {0, 0, 0, 0};
  bool keep[4] = {false, false, false, false};
#pragma unroll
  for (int p = 0; p < 4; p++) {
    float sx = 16.f * (float)(w0 + p);
    ax1[p]  = ax1_0 + sx;
    ax2v[p] = ax2_0 + sx;
    inside[p] = iny && (ax1[p] >= 0.f) && (ax2v[p] < img_w);
  }

  int ng = s_ng;
  if (inside[0] || inside[3]) {     // inside is a contiguous interval in w
    for (int gi = 0; gi < ng; gi++) {
      int g = s_gl[gi];
      float ihh = __fadd_rn(__fsub_rn(fminf(ay2, s_gy2[g]), fmaxf(ay1, s_gy1[g])), 1.0f);
      ihh = fmaxf(ihh, 0.0f);
      if (ihh <= 0.0f) continue;                 // no vertical overlap: all 4 skip
      float gx1 = s_gx1[g], gx2 = s_gx2[g];
      // widest horizontal overlap across the 4 positions; <=0 → all 4 skip
      float iwmax = __fadd_rn(__fsub_rn(fminf(ax2v[3], gx2), fmaxf(ax1[0], gx1)), 1.0f);
      if (iwmax <= 0.0f) continue;
      float ga = s_ga[g], gm = s_gm[g];
#pragma unroll
      for (int p = 0; p < 4; p++) {
        if (!inside[p]) continue;
        float iw = __fadd_rn(__fsub_rn(fminf(ax2v[p], gx2), fmaxf(ax1[p], gx1)), 1.0f);
        float inter = __fmul_rn(fmaxf(iw, 0.0f), ihh);
        if (inter <= 0.0f) continue;
        float ua = __fsub_rn(__fadd_rn(area, ga), inter);
        float tmx = __fmul_rn(mx[p], ua);        // max guard
        float bua = __fmul_rn(gm, ua);           // keep band
        if (inter > tmx * 0.9999995f || fabsf(inter - bua) <= bua * 3e-7f) {
          float v = __fdiv_rn(inter, ua);
          keep[p] = keep[p] || (v == gm);
          if (v > mx[p]) { mx[p] = v; amax[p] = g; }
        }
      }
    }
  }

  int L[4];
  float4 tgp[4];
#pragma unroll
  for (int p = 0; p < 4; p++) {
    L[p] = 2;
    if (inside[p]) L[p] = (keep[p] || mx[p] >= 0.7f) ? 1 : ((mx[p] < 0.3f) ? 0 : 2);
    tgp[p] = make_float4(0.f, 0.f, 0.f, 0.f);
    if (inside[p]) {
      int am = amax[p];
      float ecx = ax1[p] + 0.5f * ew, ecy = ay1 + 0.5f * eh;
      tgp[p].x = (s_gcx[am] - ecx) / ew;
      tgp[p].y = (s_gcy[am] - ecy) / eh;
      tgp[p].z = s_lw[am];
      tgp[p].w = s_lh[am];
    }
  }

  // ---- vector stores: label fill, 4 target planes, 8 zero weight planes ----
  const size_t OFF1 = (size_t)BB * AA * HW;
  const size_t PL   = (size_t)BB * 36 * HW;
  size_t cb = ((size_t)b * 36 + a * 4) * HW + hw0;
  float4 z4 = make_float4(0.f, 0.f, 0.f, 0.f);
  *reinterpret_cast<float4*>(&out[((size_t)b * AA + a) * HW + hw0]) =
      make_float4(-1.f, -1.f, -1.f, -1.f);
  float* tgt_o  = out + OFF1;
  float* inw_o  = out + OFF1 + PL;
  float* outw_o = out + OFF1 + 2 * PL;
  *reinterpret_cast<float4*>(&tgt_o[cb        ]) = make_float4(tgp[0].x, tgp[1].x, tgp[2].x, tgp[3].x);
  *reinterpret_cast<float4*>(&tgt_o[cb +   HW ]) = make_float4(tgp[0].y, tgp[1].y, tgp[2].y, tgp[3].y);
  *reinterpret_cast<float4*>(&tgt_o[cb + 2*HW ]) = make_float4(tgp[0].z, tgp[1].z, tgp[2].z, tgp[3].z);
  *reinterpret_cast<float4*>(&tgt_o[cb + 3*HW ]) = make_float4(tgp[0].w, tgp[1].w, tgp[2].w, tgp[3].w);
#pragma unroll
  for (int c = 0; c < 4; c++) *reinterpret_cast<float4*>(&inw_o [cb + (size_t)c * HW]) = z4;
#pragma unroll
  for (int c = 0; c < 4; c++) *reinterpret_cast<float4*>(&outw_o[cb + (size_t)c * HW]) = z4;

  // ---- RNG draws ----
  ull key[4];
  unsigned m[4];
  int cf = 0, cbg = 0, csf = 0, csb = 0;
#pragma unroll
  for (int p = 0; p < 4; p++) {
    m[p] = 0u; key[p] = 0ull;
    if (L[p] <= 1) {
      int t = (hw0 + p) * 9 + a;
      uint32_t key0 = L[p] ? kf0 : kb0, key1 = L[p] ? kf1 : kb1;
      uint32_t o0, o1;
      tf2x32(key0, key1, 0u, (uint32_t)(b * TT + t), o0, o1);
      m[p] = (o0 ^ o1) >> 9;
      key[p] = ((ull)m[p] << 16) | (unsigned)t;
      if (L[p] == 1) { cf++; if (m[p] < T_FG) csf++; }
      else           { cbg++; if (m[p] < T_BG) csb++; }
    }
  }

  // ---- warp-aggregated compaction ----
  int basef  = warp_alloc(&g_cnt_fg[b],  cf);
  int baseb  = warp_alloc(&g_cnt_bg[b],  cbg);
  int basesf = warp_alloc(&g_cnt_sfg[b], csf);
  int basesb = warp_alloc(&g_cnt_sbg[b], csb);
#pragma unroll
  for (int p = 0; p < 4; p++) {
    if (L[p] == 1) {
      g_cfg[(size_t)b * TT + basef++] = key[p];
      if (m[p] < T_FG) { if (basesf < SCAP) g_sfg[b*SCAP + basesf] = key[p]; basesf++; }
    } else if (L[p] == 0) {
      g_cbg[(size_t)b * TT + baseb++] = key[p];
      if (m[p] < T_BG) { if (basesb < SCAP) g_sbg[b*SCAP + basesb] = key[p]; basesb++; }
    }
  }
}

// ---------------- K3: exact k-smallest -> direct output scatter ----------------
__device__ __forceinline__ int blockInclScan(int local, int* s_wsum) {
  int lane = threadIdx.x & 31, wid = threadIdx.x >> 5;
  int v = local;
#pragma unroll
  for (int o = 1; o < 32; o <<= 1) { int n = __shfl_up_sync(FULLM, v, o); if (lane >= o) v += n; }
  if (lane == 31) s_wsum[wid] = v;
  __syncthreads();
  if (wid == 0) {
    int wv = s_wsum[lane];
#pragma unroll
    for (int o = 1; o < 32; o <<= 1) { int n = __shfl_up_sync(FULLM, wv, o); if (lane >= o) wv += n; }
    s_wsum[lane] = wv;
  }
  __syncthreads();
  return v + (wid ? s_wsum[wid-1] : 0);
}

__device__ __forceinline__ void scatter_keep(float* out, int b, int cls, float u, ull key) {
  const size_t OFF1 = (size_t)BB * AA * HW;
  const size_t PL   = (size_t)BB * 36 * HW;
  int t = (int)(key & 0xFFFFull);
  int a = t % 9, hw = t / 9;
  out[((size_t)b * AA + a) * HW + hw] = (float)cls;
  size_t cb = ((size_t)b * 36 + a * 4) * HW + hw;
  float* inw_o  = out + OFF1 + PL;
  float* outw_o = out + OFF1 + 2 * PL;
  if (cls) {
#pragma unroll
    for (int c = 0; c < 4; c++) inw_o[cb + (size_t)c * HW] = 1.0f;
  }
#pragma unroll
  for (int c = 0; c < 4; c++) outw_o[cb + (size_t)c * HW] = u;
}

__global__ void __launch_bounds__(1024) k3_select(float* __restrict__ out) {
  __shared__ unsigned s_hist[8192];   // fallback hist; shared-path: 2048 keys + 4096 bins
  __shared__ int s_wsum[32];
  __shared__ int s_sel[2];
  __shared__ int s_cnt;
  int b = blockIdx.x, cls = blockIdx.y, tid = threadIdx.x;

  int nfg = g_cnt_fg[b], nbg = g_cnt_bg[b];
  int kept_fg = min(nfg, FG_K);
  int kbg = RPN_BATCH_K - kept_fg;
  float u = 1.0f / (float)(kept_fg + min(nbg, kbg));
  int n = cls ? nfg : nbg;
  int k = cls ? FG_K : kbg;
  const ull* keys = (cls ? g_cfg : g_cbg) + (size_t)b * TT;

  if (n <= k) {                      // keep everything
    for (int i = tid; i < n; i += 1024) scatter_keep(out, b, cls, u, keys[i]);
    return;
  }

  // ---- fast shared-memory path ----
  int ns = cls ? g_cnt_sfg[b] : g_cnt_sbg[b];
  const ull* src = nullptr; int nm = 0;
  if (n <= SCAP)                        { src = keys; nm = n; }
  else if (ns >= k && ns <= SCAP)       { src = (cls ? g_sfg : g_sbg) + b*SCAP; nm = ns; }
  if (src) {
    ull* sk = reinterpret_cast<ull*>(s_hist);       // 2048 * 8B
    unsigned* h4 = s_hist + 4096;                   // 4096 bins
    for (int i = tid; i < nm; i += 1024) sk[i] = src[i];
    for (int i = tid; i < 4096; i += 1024) h4[i] = 0u;
    __syncthreads();
    for (int i = tid; i < nm; i += 1024)
      atomicAdd(&h4[(unsigned)(sk[i] >> 27)], 1u);  // top 12 bits of m
    __syncthreads();
    int base = tid * 4, local = 0;
#pragma unroll
    for (int j = 0; j < 4; j++) local += (int)h4[base + j];
    int incl = blockInclScan(local, s_wsum);
    int excl = incl - local;
    if (k > excl && k <= incl) {
      int c = excl;
      for (int j = 0; j < 4; j++) {
        int hh = (int)h4[base + j];
        if (c + hh >= k) { s_sel[0] = base + j; s_sel[1] = c; break; }
        c += hh;
      }
    }
    __syncthreads();
    int selbin = s_sel[0], cum = s_sel[1];
    for (int i = tid; i < nm; i += 1024) {
      ull key = sk[i];
      int bin = (int)(key >> 27);
      if (bin < selbin) {
        scatter_keep(out, b, cls, u, key);
      } else if (bin == selbin) {
        int lr = 0;
        for (int j = 0; j < nm; j++) {
          ull kj = sk[j];
          lr += ((int)(kj >> 27) == selbin) && (kj < key);
        }
        if (cum + lr < k) scatter_keep(out, b, cls, u, key);
      }
    }
    return;
  }

  // ---- fallback: global multi-level radix select (rare) ----
  ull* s_keys = reinterpret_cast<ull*>(s_hist);
  ull prefix = 0ull;
  int kk = k, shift = 26;
  for (int lvl = 0; ; lvl++) {
    shift = 26 - 13 * lvl;
    for (int i = tid; i < 8192; i += 1024) s_hist[i] = 0u;
    __syncthreads();
    for (int i = tid; i < n; i += 1024) {
      ull key = keys[i];
      if (lvl == 0 || (key >> (shift + 13)) == prefix)
        atomicAdd(&s_hist[(unsigned)(key >> shift) & 8191u], 1u);
    }
    __syncthreads();
    {
      int base = tid * 8, local = 0;
#pragma unroll
      for (int j = 0; j < 8; j++) local += (int)s_hist[base + j];
      int incl = blockInclScan(local, s_wsum);
      int excl = incl - local;
      if (kk > excl && kk <= incl) {
        int c = excl;
        for (int j = 0; j < 8; j++) {
          int hh = (int)s_hist[base + j];
          if (c + hh >= kk) { s_sel[0] = base + j; s_sel[1] = c; break; }
          c += hh;
        }
      }
      __syncthreads();
    }
    prefix = (prefix << 13) | (unsigned)s_sel[0];
    kk -= s_sel[1];
    int bc = (int)s_hist[s_sel[0]];
    __syncthreads();
    if (bc <= 4096 || shift == 0) break;
  }
  if (tid == 0) s_cnt = 0;
  __syncthreads();
  for (int i = tid; i < n; i += 1024) {
    ull key = keys[i];
    ull hi = key >> shift;
    if (hi < prefix) scatter_keep(out, b, cls, u, key);
    else if (hi == prefix) {
      int j = atomicAdd(&s_cnt, 1);
      s_keys[j] = key;
    }
  }
  __syncthreads();
  int cnt = s_cnt;
  for (int jj = tid; jj < cnt; jj += 1024) {
    ull kj = s_keys[jj];
    int r = 0;
    for (int i = 0; i < cnt; i++) r += (s_keys[i] < kj);
    if (r < kk) scatter_keep(out, b, cls, u, kj);
  }
}

// ---------------- host ----------------
extern "C" void kernel_launch(void* const* d_in, const int* in_sizes, int n_in,
                              void* d_out, int out_size) {
  const float* gt     = (const float*)d_in[1];   // gt_boxes [32,20,5]
  const float* iminfo = (const float*)d_in[2];   // im_info [32,3]
  float* out = (float*)d_out;

  uint32_t kf0, kf1, kb0, kb1;
  tf2x32(0u, 42u, 0u, 0u, kf0, kf1);
  tf2x32(0u, 42u, 0u, 1u, kb0, kb1);

  k1_gtmax <<<dim3(NGT, BB), 256>>>(gt, iminfo);
  k2_main  <<<dim3(5, AA, BB), 320>>>(gt, iminfo, kf0, kf1, kb0, kb1, out);
  k3_select<<<dim3(BB, 2), 1024>>>(out);
}

// round 11
// speedup vs baseline: 1.9826x; 1.1140x over previous
#include <cuda_runtime.h>
#include <stdint.h>

#define BB 32
#define NGT 20
#define FH 64
#define FW 100
#define AA 9
#define HW (FH*FW)      // 6400
#define TT (HW*AA)      // 57600
#define FG_K 128
#define RPN_BATCH_K 256
#define FULLM 0xffffffffu
#define SCAP 2048        // small-list capacity
#define T_FG (1u<<20)    // fg prune threshold on 23-bit m
#define T_BG (1u<<17)    // bg prune threshold on 23-bit m

typedef unsigned long long ull;

__device__ __constant__ float c_anchors[AA*4] = {
  -84.f,  -40.f,  99.f,  55.f,
 -176.f,  -88.f, 191.f, 103.f,
 -360.f, -184.f, 375.f, 199.f,
  -56.f,  -56.f,  71.f,  71.f,
 -120.f, -120.f, 135.f, 135.f,
 -248.f, -248.f, 263.f, 263.f,
  -36.f,  -80.f,  51.f,  95.f,
  -80.f, -168.f,  95.f, 183.f,
 -168.f, -344.f, 183.f, 359.f
};

// ---------------- Threefry-2x32 (20 rounds), matches JAX partitionable ----------------
__host__ __device__ __forceinline__ void tf2x32(uint32_t k0, uint32_t k1,
                                                uint32_t x0, uint32_t x1,
                                                uint32_t& o0, uint32_t& o1) {
  uint32_t ks2 = k0 ^ k1 ^ 0x1BD11BDAu;
  x0 += k0; x1 += k1;
#define TF_RND(r) { x0 += x1; x1 = (x1 << (r)) | (x1 >> (32 - (r))); x1 ^= x0; }
  TF_RND(13) TF_RND(15) TF_RND(26) TF_RND(6)   x0 += k1;  x1 += ks2 + 1u;
  TF_RND(17) TF_RND(29) TF_RND(16) TF_RND(24)  x0 += ks2; x1 += k0  + 2u;
  TF_RND(13) TF_RND(15) TF_RND(26) TF_RND(6)   x0 += k0;  x1 += k1  + 3u;
  TF_RND(17) TF_RND(29) TF_RND(16) TF_RND(24)  x0 += k1;  x1 += ks2 + 4u;
  TF_RND(13) TF_RND(15) TF_RND(26) TF_RND(6)   x0 += ks2; x1 += k0  + 5u;
#undef TF_RND
  o0 = x0; o1 = x1;
}

// ---------------- scratch (device globals; no allocations) ----------------
__device__ unsigned int  g_gtmax_part[BB*NGT*AA];  // per-(b,g,a) partial max (0 = none)
__device__ int           g_cnt_fg[BB];
__device__ int           g_cnt_bg[BB];
__device__ int           g_cnt_sfg[BB];
__device__ int           g_cnt_sbg[BB];
__device__ ull           g_cfg[(size_t)BB*TT];  // fg full candidate keys (m<<16)|t
__device__ ull           g_cbg[(size_t)BB*TT];  // bg full candidate keys
__device__ ull           g_sfg[BB*SCAP];        // fg pruned keys (m < T_FG)
__device__ ull           g_sbg[BB*SCAP];        // bg pruned keys (m < T_BG)

// ---------------- K1: one block per (b,g,a); partial max, no atomics ----------------
__global__ void __launch_bounds__(96) k1_gtmax(const float* __restrict__ gt,
                                               const float* __restrict__ iminfo) {
  int a = blockIdx.x, g = blockIdx.y, b = blockIdx.z;
  int tid = threadIdx.x, lane = tid & 31, wrp = tid >> 5;   // 3 warps
  if (a == 0 && g == 0 && tid == 0) {
    g_cnt_fg[b] = 0; g_cnt_bg[b] = 0;
    g_cnt_sfg[b] = 0; g_cnt_sbg[b] = 0;
  }
  __shared__ unsigned s_best[3];
  int part_idx = (b*NGT + g)*AA + a;

  float gx1 = __ldg(&gt[(b*NGT+g)*5+0]);
  float gy1 = __ldg(&gt[(b*NGT+g)*5+1]);
  float gx2 = __ldg(&gt[(b*NGT+g)*5+2]);
  float gy2 = __ldg(&gt[(b*NGT+g)*5+3]);
  float gw = __fadd_rn(__fsub_rn(gx2, gx1), 1.0f);
  float gh = __fadd_rn(__fsub_rn(gy2, gy1), 1.0f);
  if (gw == 1.0f && gh == 1.0f) {              // zero gt
    if (tid == 0) g_gtmax_part[part_idx] = 0u;
    return;
  }
  float ga = __fmul_rn(gw, gh);
  float img_h = iminfo[0], img_w = iminfo[1];

  float ax1_0 = c_anchors[a*4+0], ay1_0 = c_anchors[a*4+1];
  float ax2_0 = c_anchors[a*4+2], ay2_0 = c_anchors[a*4+3];
  // inside range ∩ (widened) overlap range
  int w0 = max(max((int)ceilf(-ax1_0 * 0.0625f),
                   (int)floorf((gx1 - ax2_0) * 0.0625f) - 1), 0);
  int w1 = min(min((int)floorf((img_w - 1.0f - ax2_0) * 0.0625f),
                   (int)ceilf((gx2 - ax1_0) * 0.0625f) + 1), FW-1);
  int h0 = max(max((int)ceilf(-ay1_0 * 0.0625f),
                   (int)floorf((gy1 - ay2_0) * 0.0625f) - 1), 0);
  int h1 = min(min((int)floorf((img_h - 1.0f - ay2_0) * 0.0625f),
                   (int)ceilf((gy2 - ay1_0) * 0.0625f) + 1), FH-1);
  if (w1 < w0 || h1 < h0) {
    if (tid == 0) g_gtmax_part[part_idx] = 0u;
    return;
  }
  float aw = __fadd_rn(__fsub_rn(ax2_0, ax1_0), 1.0f);
  float ah = __fadd_rn(__fsub_rn(ay2_0, ay1_0), 1.0f);
  float area = __fmul_rn(aw, ah);

  float bestf = 0.0f;
  for (int hh = h0 + wrp; hh <= h1; hh += 3) {
    float sy = 16.f * (float)hh;
    float ay1 = ay1_0 + sy, ay2 = ay2_0 + sy;
    float ihh = __fadd_rn(__fsub_rn(fminf(ay2, gy2), fmaxf(ay1, gy1)), 1.0f);
    ihh = fmaxf(ihh, 0.0f);
    if (ihh <= 0.0f) continue;
    for (int w = w0 + lane; w <= w1; w += 32) {
      float sx = 16.f * (float)w;
      float ax1 = ax1_0 + sx, ax2 = ax2_0 + sx;
      float iw = __fadd_rn(__fsub_rn(fminf(ax2, gx2), fmaxf(ax1, gx1)), 1.0f);
      float inter = __fmul_rn(fmaxf(iw, 0.0f), ihh);
      if (inter > 0.0f) {
        float ua = __fsub_rn(__fadd_rn(area, ga), inter);
        // guarded division: only pairs that can exceed current best
        if (inter > __fmul_rn(bestf, ua) * 0.9999995f) {
          float v = __fdiv_rn(inter, ua);
          if (v > bestf) bestf = v;
        }
      }
    }
  }
  unsigned fu = (bestf > 0.0f) ? (__float_as_uint(bestf) | 0x80000000u) : 0u;
  fu = __reduce_max_sync(FULLM, fu);
  if (lane == 0) s_best[wrp] = fu;
  __syncthreads();
  if (tid == 0)
    g_gtmax_part[part_idx] = max(max(s_best[0], s_best[1]), s_best[2]);
}

// warp-aggregated allocation: returns base index for this thread's cnt items
__device__ __forceinline__ int warp_alloc(int* ctr, int cnt) {
  int lane = threadIdx.x & 31;
  int v = cnt;
#pragma unroll
  for (int o = 1; o < 32; o <<= 1) {
    int n = __shfl_up_sync(FULLM, v, o);
    if (lane >= o) v += n;
  }
  int total = __shfl_sync(FULLM, v, 31);
  int base = 0;
  if (lane == 31 && total) base = atomicAdd(ctr, total);
  base = __shfl_sync(FULLM, base, 31);
  return base + v - cnt;
}

// ---------------- K2: 4-wide: fill+targets+labels+RNG+compaction ----------------
__global__ void __launch_bounds__(320) k2_main(
    const float* __restrict__ gt, const float* __restrict__ iminfo,
    uint32_t kf0, uint32_t kf1, uint32_t kb0, uint32_t kb1,
    float* __restrict__ out) {
  __shared__ float s_gx1[NGT], s_gy1[NGT], s_gx2[NGT], s_gy2[NGT];
  __shared__ float s_ga[NGT], s_gcx[NGT], s_gcy[NGT], s_lw[NGT], s_lh[NGT], s_gm[NGT];
  __shared__ int s_gl[NGT];
  __shared__ int s_ng;
  int b = blockIdx.z, a = blockIdx.y, tid = threadIdx.x;
  int hw0 = (blockIdx.x * 320 + tid) * 4;       // groups of 4 never cross a row (100%4==0)

  float ax1_0 = c_anchors[a*4+0], ay1_0 = c_anchors[a*4+1];
  float ax2_0 = c_anchors[a*4+2], ay2_0 = c_anchors[a*4+3];
  float ew = __fadd_rn(__fsub_rn(ax2_0, ax1_0), 1.0f);
  float eh = __fadd_rn(__fsub_rn(ay2_0, ay1_0), 1.0f);
  float area = __fmul_rn(ew, eh);

  if (tid < 32) {
    bool nz = false;
    if (tid < NGT) {
      float x1 = gt[(b*NGT+tid)*5+0], y1 = gt[(b*NGT+tid)*5+1];
      float x2 = gt[(b*NGT+tid)*5+2], y2 = gt[(b*NGT+tid)*5+3];
      float gw = __fadd_rn(__fsub_rn(x2, x1), 1.0f);
      float gh = __fadd_rn(__fsub_rn(y2, y1), 1.0f);
      nz = !(gw == 1.0f && gh == 1.0f);
      s_gx1[tid] = x1; s_gy1[tid] = y1; s_gx2[tid] = x2; s_gy2[tid] = y2;
      s_ga[tid]  = __fmul_rn(gw, gh);
      s_gcx[tid] = x1 + 0.5f * gw;
      s_gcy[tid] = y1 + 0.5f * gh;
      s_lw[tid]  = logf(gw / ew);
      s_lh[tid]  = logf(gh / eh);
      unsigned u_ = 0u;
#pragma unroll
      for (int aa = 0; aa < AA; aa++)
        u_ = max(u_, g_gtmax_part[(b*NGT + tid)*AA + aa]);
      s_gm[tid]  = u_ ? __uint_as_float(u_ ^ 0x80000000u) : -999.0f;
    }
    unsigned mask = __ballot_sync(FULLM, nz);
    if (tid == 0) s_ng = __popc(mask);
    if (nz) s_gl[__popc(mask & ((1u << tid) - 1u))] = tid;
  }
  __syncthreads();

  float img_h = iminfo[0], img_w = iminfo[1];
  int h = hw0 / FW, w0 = hw0 - h * FW;
  float sy = 16.f * (float)h;
  float ay1 = ay1_0 + sy, ay2 = ay2_0 + sy;
  bool iny = (ay1 >= 0.f) && (ay2 < img_h);

  float ax1[4], ax2v[4];
  bool inside[4];
  float mx[4] = {0.f, 0.f, 0.f, 0.f};
  int amax[4] = {0, 0, 0, 0};
  bool keep[4] = {false, false, false, false};
#pragma unroll
  for (int p = 0; p < 4; p++) {
    float sx = 16.f * (float)(w0 + p);
    ax1[p]  = ax1_0 + sx;
    ax2v[p] = ax2_0 + sx;
    inside[p] = iny && (ax1[p] >= 0.f) && (ax2v[p] < img_w);
  }

  int ng = s_ng;
  if (inside[0] || inside[3]) {     // inside is a contiguous interval in w
    for (int gi = 0; gi < ng; gi++) {
      int g = s_gl[gi];
      float ihh = __fadd_rn(__fsub_rn(fminf(ay2, s_gy2[g]), fmaxf(ay1, s_gy1[g])), 1.0f);
      ihh = fmaxf(ihh, 0.0f);
      if (ihh <= 0.0f) continue;                 // no vertical overlap: all 4 skip
      float gx1 = s_gx1[g], gx2 = s_gx2[g];
      float iwmax = __fadd_rn(__fsub_rn(fminf(ax2v[3], gx2), fmaxf(ax1[0], gx1)), 1.0f);
      if (iwmax <= 0.0f) continue;
      float ga = s_ga[g], gm = s_gm[g];
#pragma unroll
      for (int p = 0; p < 4; p++) {
        if (!inside[p]) continue;
        float iw = __fadd_rn(__fsub_rn(fminf(ax2v[p], gx2), fmaxf(ax1[p], gx1)), 1.0f);
        float inter = __fmul_rn(fmaxf(iw, 0.0f), ihh);
        if (inter <= 0.0f) continue;
        float ua = __fsub_rn(__fadd_rn(area, ga), inter);
        float tmx = __fmul_rn(mx[p], ua);        // max guard
        float bua = __fmul_rn(gm, ua);           // keep band
        if (inter > tmx * 0.9999995f || fabsf(inter - bua) <= bua * 3e-7f) {
          float v = __fdiv_rn(inter, ua);
          keep[p] = keep[p] || (v == gm);
          if (v > mx[p]) { mx[p] = v; amax[p] = g; }
        }
      }
    }
  }

  int L[4];
  float4 tgp[4];
#pragma unroll
  for (int p = 0; p < 4; p++) {
    L[p] = 2;
    if (inside[p]) L[p] = (keep[p] || mx[p] >= 0.7f) ? 1 : ((mx[p] < 0.3f) ? 0 : 2);
    tgp[p] = make_float4(0.f, 0.f, 0.f, 0.f);
    if (inside[p]) {
      int am = amax[p];
      float ecx = ax1[p] + 0.5f * ew, ecy = ay1 + 0.5f * eh;
      tgp[p].x = __fdividef(s_gcx[am] - ecx, ew);
      tgp[p].y = __fdividef(s_gcy[am] - ecy, eh);
      tgp[p].z = s_lw[am];
      tgp[p].w = s_lh[am];
    }
  }

  // ---- vector stores: label fill, 4 target planes, 8 zero weight planes ----
  const size_t OFF1 = (size_t)BB * AA * HW;
  const size_t PL   = (size_t)BB * 36 * HW;
  size_t cb = ((size_t)b * 36 + a * 4) * HW + hw0;
  float4 z4 = make_float4(0.f, 0.f, 0.f, 0.f);
  *reinterpret_cast<float4*>(&out[((size_t)b * AA + a) * HW + hw0]) =
      make_float4(-1.f, -1.f, -1.f, -1.f);
  float* tgt_o  = out + OFF1;
  float* inw_o  = out + OFF1 + PL;
  float* outw_o = out + OFF1 + 2 * PL;
  *reinterpret_cast<float4*>(&tgt_o[cb        ]) = make_float4(tgp[0].x, tgp[1].x, tgp[2].x, tgp[3].x);
  *reinterpret_cast<float4*>(&tgt_o[cb +   HW ]) = make_float4(tgp[0].y, tgp[1].y, tgp[2].y, tgp[3].y);
  *reinterpret_cast<float4*>(&tgt_o[cb + 2*HW ]) = make_float4(tgp[0].z, tgp[1].z, tgp[2].z, tgp[3].z);
  *reinterpret_cast<float4*>(&tgt_o[cb + 3*HW ]) = make_float4(tgp[0].w, tgp[1].w, tgp[2].w, tgp[3].w);
#pragma unroll
  for (int c = 0; c < 4; c++) *reinterpret_cast<float4*>(&inw_o [cb + (size_t)c * HW]) = z4;
#pragma unroll
  for (int c = 0; c < 4; c++) *reinterpret_cast<float4*>(&outw_o[cb + (size_t)c * HW]) = z4;

  // ---- RNG draws ----
  ull key[4];
  unsigned m[4];
  int cf = 0, cbg = 0, csf = 0, csb = 0;
#pragma unroll
  for (int p = 0; p < 4; p++) {
    m[p] = 0u; key[p] = 0ull;
    if (L[p] <= 1) {
      int t = (hw0 + p) * 9 + a;
      uint32_t key0 = L[p] ? kf0 : kb0, key1 = L[p] ? kf1 : kb1;
      uint32_t o0, o1;
      tf2x32(key0, key1, 0u, (uint32_t)(b * TT + t), o0, o1);
      m[p] = (o0 ^ o1) >> 9;
      key[p] = ((ull)m[p] << 16) | (unsigned)t;
      if (L[p] == 1) { cf++; if (m[p] < T_FG) csf++; }
      else           { cbg++; if (m[p] < T_BG) csb++; }
    }
  }

  // ---- warp-aggregated compaction ----
  int basef  = warp_alloc(&g_cnt_fg[b],  cf);
  int baseb  = warp_alloc(&g_cnt_bg[b],  cbg);
  int basesf = warp_alloc(&g_cnt_sfg[b], csf);
  int basesb = warp_alloc(&g_cnt_sbg[b], csb);
#pragma unroll
  for (int p = 0; p < 4; p++) {
    if (L[p] == 1) {
      g_cfg[(size_t)b * TT + basef++] = key[p];
      if (m[p] < T_FG) { if (basesf < SCAP) g_sfg[b*SCAP + basesf] = key[p]; basesf++; }
    } else if (L[p] == 0) {
      g_cbg[(size_t)b * TT + baseb++] = key[p];
      if (m[p] < T_BG) { if (basesb < SCAP) g_sbg[b*SCAP + basesb] = key[p]; basesb++; }
    }
  }
}

// ---------------- K3: exact k-smallest -> direct output scatter ----------------
__device__ __forceinline__ int blockInclScan(int local, int* s_wsum) {
  int lane = threadIdx.x & 31, wid = threadIdx.x >> 5;
  int v = local;
#pragma unroll
  for (int o = 1; o < 32; o <<= 1) { int n = __shfl_up_sync(FULLM, v, o); if (lane >= o) v += n; }
  if (lane == 31) s_wsum[wid] = v;
  __syncthreads();
  if (wid == 0) {
    int wv = s_wsum[lane];
#pragma unroll
    for (int o = 1; o < 32; o <<= 1) { int n = __shfl_up_sync(FULLM, wv, o); if (lane >= o) wv += n; }
    s_wsum[lane] = wv;
  }
  __syncthreads();
  return v + (wid ? s_wsum[wid-1] : 0);
}

__device__ __forceinline__ void scatter_keep(float* out, int b, int cls, float u, ull key) {
  const size_t OFF1 = (size_t)BB * AA * HW;
  const size_t PL   = (size_t)BB * 36 * HW;
  int t = (int)(key & 0xFFFFull);
  int a = t % 9, hw = t / 9;
  out[((size_t)b * AA + a) * HW + hw] = (float)cls;
  size_t cb = ((size_t)b * 36 + a * 4) * HW + hw;
  float* inw_o  = out + OFF1 + PL;
  float* outw_o = out + OFF1 + 2 * PL;
  if (cls) {
#pragma unroll
    for (int c = 0; c < 4; c++) inw_o[cb + (size_t)c * HW] = 1.0f;
  }
#pragma unroll
  for (int c = 0; c < 4; c++) outw_o[cb + (size_t)c * HW] = u;
}

__global__ void __launch_bounds__(1024) k3_select(float* __restrict__ out) {
  __shared__ unsigned s_hist[8192];   // fallback hist; shared-path: 2048 keys + 4096 bins
  __shared__ int s_wsum[32];
  __shared__ int s_sel[2];
  __shared__ int s_cnt;
  int b = blockIdx.x, cls = blockIdx.y, tid = threadIdx.x;

  int nfg = g_cnt_fg[b], nbg = g_cnt_bg[b];
  int kept_fg = min(nfg, FG_K);
  int kbg = RPN_BATCH_K - kept_fg;
  float u = 1.0f / (float)(kept_fg + min(nbg, kbg));
  int n = cls ? nfg : nbg;
  int k = cls ? FG_K : kbg;
  const ull* keys = (cls ? g_cfg : g_cbg) + (size_t)b * TT;

  if (n <= k) {                      // keep everything
    for (int i = tid; i < n; i += 1024) scatter_keep(out, b, cls, u, keys[i]);
    return;
  }

  // ---- fast shared-memory path ----
  int ns = cls ? g_cnt_sfg[b] : g_cnt_sbg[b];
  const ull* src = nullptr; int nm = 0;
  if (n <= SCAP)                        { src = keys; nm = n; }
  else if (ns >= k && ns <= SCAP)       { src = (cls ? g_sfg : g_sbg) + b*SCAP; nm = ns; }
  if (src) {
    ull* sk = reinterpret_cast<ull*>(s_hist);       // 2048 * 8B
    unsigned* h4 = s_hist + 4096;                   // 4096 bins
    for (int i = tid; i < nm; i += 1024) sk[i] = src[i];
    for (int i = tid; i < 4096; i += 1024) h4[i] = 0u;
    __syncthreads();
    for (int i = tid; i < nm; i += 1024)
      atomicAdd(&h4[(unsigned)(sk[i] >> 27)], 1u);  // top 12 bits of m
    __syncthreads();
    int base = tid * 4, local = 0;
#pragma unroll
    for (int j = 0; j < 4; j++) local += (int)h4[base + j];
    int incl = blockInclScan(local, s_wsum);
    int excl = incl - local;
    if (k > excl && k <= incl) {
      int c = excl;
      for (int j = 0; j < 4; j++) {
        int hh = (int)h4[base + j];
        if (c + hh >= k) { s_sel[0] = base + j; s_sel[1] = c; break; }
        c += hh;
      }
    }
    __syncthreads();
    int selbin = s_sel[0], cum = s_sel[1];
    for (int i = tid; i < nm; i += 1024) {
      ull key = sk[i];
      int bin = (int)(key >> 27);
      if (bin < selbin) {
        scatter_keep(out, b, cls, u, key);
      } else if (bin == selbin) {
        int lr = 0;
        for (int j = 0; j < nm; j++) {
          ull kj = sk[j];
          lr += ((int)(kj >> 27) == selbin) && (kj < key);
        }
        if (cum + lr < k) scatter_keep(out, b, cls, u, key);
      }
    }
    return;
  }

  // ---- fallback: global multi-level radix select (rare) ----
  ull* s_keys = reinterpret_cast<ull*>(s_hist);
  ull prefix = 0ull;
  int kk = k, shift = 26;
  for (int lvl = 0; ; lvl++) {
    shift = 26 - 13 * lvl;
    for (int i = tid; i < 8192; i += 1024) s_hist[i] = 0u;
    __syncthreads();
    for (int i = tid; i < n; i += 1024) {
      ull key = keys[i];
      if (lvl == 0 || (key >> (shift + 13)) == prefix)
        atomicAdd(&s_hist[(unsigned)(key >> shift) & 8191u], 1u);
    }
    __syncthreads();
    {
      int base = tid * 8, local = 0;
#pragma unroll
      for (int j = 0; j < 8; j++) local += (int)s_hist[base + j];
      int incl = blockInclScan(local, s_wsum);
      int excl = incl - local;
      if (kk > excl && kk <= incl) {
        int c = excl;
        for (int j = 0; j < 8; j++) {
          int hh = (int)s_hist[base + j];
          if (c + hh >= kk) { s_sel[0] = base + j; s_sel[1] = c; break; }
          c += hh;
        }
      }
      __syncthreads();
    }
    prefix = (prefix << 13) | (unsigned)s_sel[0];
    kk -= s_sel[1];
    int bc = (int)s_hist[s_sel[0]];
    __syncthreads();
    if (bc <= 4096 || shift == 0) break;
  }
  if (tid == 0) s_cnt = 0;
  __syncthreads();
  for (int i = tid; i < n; i += 1024) {
    ull key = keys[i];
    ull hi = key >> shift;
    if (hi < prefix) scatter_keep(out, b, cls, u, key);
    else if (hi == prefix) {
      int j = atomicAdd(&s_cnt, 1);
      s_keys[j] = key;
    }
  }
  __syncthreads();
  int cnt = s_cnt;
  for (int jj = tid; jj < cnt; jj += 1024) {
    ull kj = s_keys[jj];
    int r = 0;
    for (int i = 0; i < cnt; i++) r += (s_keys[i] < kj);
    if (r < kk) scatter_keep(out, b, cls, u, kj);
  }
}

// ---------------- host ----------------
extern "C" void kernel_launch(void* const* d_in, const int* in_sizes, int n_in,
                              void* d_out, int out_size) {
  const float* gt     = (const float*)d_in[1];   // gt_boxes [32,20,5]
  const float* iminfo = (const float*)d_in[2];   // im_info [32,3]
  float* out = (float*)d_out;

  uint32_t kf0, kf1, kb0, kb1;
  tf2x32(0u, 42u, 0u, 0u, kf0, kf1);
  tf2x32(0u, 42u, 0u, 1u, kb0, kb1);

  k1_gtmax <<<dim3(AA, NGT, BB), 96>>>(gt, iminfo);
  k2_main  <<<dim3(5, AA, BB), 320>>>(gt, iminfo, kf0, kf1, kb0, kb1, out);
  k3_select<<<dim3(BB, 2), 1024>>>(out);
}

// round 12
// speedup vs baseline: 2.3544x; 1.1875x over previous
#include <cuda_runtime.h>
#include <stdint.h>

#define BB 32
#define NGT 20
#define FH 64
#define FW 100
#define AA 9
#define HW (FH*FW)      // 6400
#define TT (HW*AA)      // 57600
#define FG_K 128
#define RPN_BATCH_K 256
#define FULLM 0xffffffffu
#define SCAP 2048        // small-list capacity
#define T_FG (1u<<20)    // fg prune threshold on 23-bit m
#define T_BG (1u<<17)    // bg prune threshold on 23-bit m

typedef unsigned long long ull;

__device__ __constant__ float c_anchors[AA*4] = {
  -84.f,  -40.f,  99.f,  55.f,
 -176.f,  -88.f, 191.f, 103.f,
 -360.f, -184.f, 375.f, 199.f,
  -56.f,  -56.f,  71.f,  71.f,
 -120.f, -120.f, 135.f, 135.f,
 -248.f, -248.f, 263.f, 263.f,
  -36.f,  -80.f,  51.f,  95.f,
  -80.f, -168.f,  95.f, 183.f,
 -168.f, -344.f, 183.f, 359.f
};

// ---------------- Threefry-2x32 (20 rounds), matches JAX partitionable ----------------
__host__ __device__ __forceinline__ void tf2x32(uint32_t k0, uint32_t k1,
                                                uint32_t x0, uint32_t x1,
                                                uint32_t& o0, uint32_t& o1) {
  uint32_t ks2 = k0 ^ k1 ^ 0x1BD11BDAu;
  x0 += k0; x1 += k1;
#define TF_RND(r) { x0 += x1; x1 = (x1 << (r)) | (x1 >> (32 - (r))); x1 ^= x0; }
  TF_RND(13) TF_RND(15) TF_RND(26) TF_RND(6)   x0 += k1;  x1 += ks2 + 1u;
  TF_RND(17) TF_RND(29) TF_RND(16) TF_RND(24)  x0 += ks2; x1 += k0  + 2u;
  TF_RND(13) TF_RND(15) TF_RND(26) TF_RND(6)   x0 += k0;  x1 += k1  + 3u;
  TF_RND(17) TF_RND(29) TF_RND(16) TF_RND(24)  x0 += k1;  x1 += ks2 + 4u;
  TF_RND(13) TF_RND(15) TF_RND(26) TF_RND(6)   x0 += ks2; x1 += k0  + 5u;
#undef TF_RND
  o0 = x0; o1 = x1;
}

// ---------------- scratch (device globals; no allocations) ----------------
__device__ unsigned int  g_gtmax[BB*NGT];       // biased-float max (0 = none)
__device__ int           g_cnt_fg[BB];
__device__ int           g_cnt_bg[BB];
__device__ int           g_cnt_sfg[BB];
__device__ int           g_cnt_sbg[BB];
__device__ ull           g_cfg[(size_t)BB*TT];  // fg full candidate keys (m<<16)|t
__device__ ull           g_cbg[(size_t)BB*TT];  // bg full candidate keys
__device__ ull           g_sfg[BB*SCAP];        // fg pruned keys (m < T_FG)
__device__ ull           g_sbg[BB*SCAP];        // bg pruned keys (m < T_BG)

// max over integer shift s in [i0,i1] of the exact float axis-overlap
// iw(s) = rn(rn(min(A2+16s,G2) - max(A1+16s,G1)) + 1); concave w/ plateau.
__device__ __forceinline__ float axis_max(float A1, float A2, float G1, float G2,
                                          int i0, int i1) {
  float p1 = (G1 - A1) * 0.0625f;
  float p2 = (G2 - A2) * 0.0625f;
  int c0 = (int)floorf(fminf(p1, p2));
  int c2 = (int)floorf(fmaxf(p1, p2));
  int cand[6] = {i0, i1, c0, c0 + 1, c2, c2 + 1};
  float best = -1e30f;
#pragma unroll
  for (int j = 0; j < 6; j++) {
    int s = min(max(cand[j], i0), i1);
    float fs = 16.f * (float)s;
    float v = __fadd_rn(__fsub_rn(fminf(A2 + fs, G2), fmaxf(A1 + fs, G1)), 1.0f);
    best = fmaxf(best, v);
  }
  return best;
}

// ---------------- K0: analytic per-(b,g) max IoU over inside anchors ----------------
__global__ void __launch_bounds__(192) k0_gtmax(const float* __restrict__ gt,
                                                const float* __restrict__ iminfo) {
  int b = blockIdx.x, tid = threadIdx.x;
  __shared__ unsigned s_gm[NGT];
  if (tid < NGT) s_gm[tid] = 0u;
  if (tid == 190) {
    g_cnt_fg[b] = 0; g_cnt_bg[b] = 0;
    g_cnt_sfg[b] = 0; g_cnt_sbg[b] = 0;
  }
  __syncthreads();
  if (tid < NGT * AA) {
    int g = tid / AA, a = tid - g * AA;
    float gx1 = __ldg(&gt[(b*NGT+g)*5+0]);
    float gy1 = __ldg(&gt[(b*NGT+g)*5+1]);
    float gx2 = __ldg(&gt[(b*NGT+g)*5+2]);
    float gy2 = __ldg(&gt[(b*NGT+g)*5+3]);
    float gw = __fadd_rn(__fsub_rn(gx2, gx1), 1.0f);
    float gh = __fadd_rn(__fsub_rn(gy2, gy1), 1.0f);
    if (!(gw == 1.0f && gh == 1.0f)) {            // non-zero gt
      float ga = __fmul_rn(gw, gh);
      float img_h = iminfo[0], img_w = iminfo[1];
      float ax1_0 = c_anchors[a*4+0], ay1_0 = c_anchors[a*4+1];
      float ax2_0 = c_anchors[a*4+2], ay2_0 = c_anchors[a*4+3];
      int wi0 = max((int)ceilf(-ax1_0 * 0.0625f), 0);
      int wi1 = min((int)floorf((img_w - 1.0f - ax2_0) * 0.0625f), FW-1);
      int hi0 = max((int)ceilf(-ay1_0 * 0.0625f), 0);
      int hi1 = min((int)floorf((img_h - 1.0f - ay2_0) * 0.0625f), FH-1);
      if (wi0 <= wi1 && hi0 <= hi1) {
        float iwb = axis_max(ax1_0, ax2_0, gx1, gx2, wi0, wi1);
        float ihb = axis_max(ay1_0, ay2_0, gy1, gy2, hi0, hi1);
        if (iwb > 0.0f && ihb > 0.0f) {
          float aw = __fadd_rn(__fsub_rn(ax2_0, ax1_0), 1.0f);
          float ah = __fadd_rn(__fsub_rn(ay2_0, ay1_0), 1.0f);
          float area = __fmul_rn(aw, ah);
          float inter = __fmul_rn(iwb, ihb);
          float ua = __fsub_rn(__fadd_rn(area, ga), inter);
          float v  = __fdiv_rn(inter, ua);
          atomicMax(&s_gm[g], __float_as_uint(v) | 0x80000000u);
        }
      }
    }
  }
  __syncthreads();
  if (tid < NGT) g_gtmax[b*NGT + tid] = s_gm[tid];
}

// warp-aggregated allocation: returns base index for this thread's cnt items
__device__ __forceinline__ int warp_alloc(int* ctr, int cnt) {
  int lane = threadIdx.x & 31;
  int v = cnt;
#pragma unroll
  for (int o = 1; o < 32; o <<= 1) {
    int n = __shfl_up_sync(FULLM, v, o);
    if (lane >= o) v += n;
  }
  int total = __shfl_sync(FULLM, v, 31);
  int base = 0;
  if (lane == 31 && total) base = atomicAdd(ctr, total);
  base = __shfl_sync(FULLM, base, 31);
  return base + v - cnt;
}

// ---------------- K2: 4-wide: fill+targets+labels+RNG+compaction ----------------
__global__ void __launch_bounds__(320) k2_main(
    const float* __restrict__ gt, const float* __restrict__ iminfo,
    uint32_t kf0, uint32_t kf1, uint32_t kb0, uint32_t kb1,
    float* __restrict__ out) {
  __shared__ float s_gx1[NGT], s_gy1[NGT], s_gx2[NGT], s_gy2[NGT];
  __shared__ float s_ga[NGT], s_gcx[NGT], s_gcy[NGT], s_lw[NGT], s_lh[NGT], s_gm[NGT];
  __shared__ int s_gl[NGT];
  __shared__ int s_ng;
  int b = blockIdx.z, a = blockIdx.y, tid = threadIdx.x;
  int hw0 = (blockIdx.x * 320 + tid) * 4;       // groups of 4 never cross a row (100%4==0)

  float ax1_0 = c_anchors[a*4+0], ay1_0 = c_anchors[a*4+1];
  float ax2_0 = c_anchors[a*4+2], ay2_0 = c_anchors[a*4+3];
  float ew = __fadd_rn(__fsub_rn(ax2_0, ax1_0), 1.0f);
  float eh = __fadd_rn(__fsub_rn(ay2_0, ay1_0), 1.0f);
  float area = __fmul_rn(ew, eh);

  if (tid < 32) {
    bool nz = false;
    if (tid < NGT) {
      float x1 = gt[(b*NGT+tid)*5+0], y1 = gt[(b*NGT+tid)*5+1];
      float x2 = gt[(b*NGT+tid)*5+2], y2 = gt[(b*NGT+tid)*5+3];
      float gw = __fadd_rn(__fsub_rn(x2, x1), 1.0f);
      float gh = __fadd_rn(__fsub_rn(y2, y1), 1.0f);
      nz = !(gw == 1.0f && gh == 1.0f);
      s_gx1[tid] = x1; s_gy1[tid] = y1; s_gx2[tid] = x2; s_gy2[tid] = y2;
      s_ga[tid]  = __fmul_rn(gw, gh);
      s_gcx[tid] = x1 + 0.5f * gw;
      s_gcy[tid] = y1 + 0.5f * gh;
      s_lw[tid]  = logf(gw / ew);
      s_lh[tid]  = logf(gh / eh);
      unsigned u_ = g_gtmax[b*NGT + tid];
      s_gm[tid]  = u_ ? __uint_as_float(u_ ^ 0x80000000u) : -999.0f;
    }
    unsigned mask = __ballot_sync(FULLM, nz);
    if (tid == 0) s_ng = __popc(mask);
    if (nz) s_gl[__popc(mask & ((1u << tid) - 1u))] = tid;
  }
  __syncthreads();

  float img_h = iminfo[0], img_w = iminfo[1];
  int h = hw0 / FW, w0 = hw0 - h * FW;
  float sy = 16.f * (float)h;
  float ay1 = ay1_0 + sy, ay2 = ay2_0 + sy;
  bool iny = (ay1 >= 0.f) && (ay2 < img_h);

  float ax1[4], ax2v[4];
  bool inside[4];
  float mx[4] = {0.f, 0.f, 0.f, 0.f};
  int amax[4] = {0, 0, 0, 0};
  bool keep[4] = {false, false, false, false};
#pragma unroll
  for (int p = 0; p < 4; p++) {
    float sx = 16.f * (float)(w0 + p);
    ax1[p]  = ax1_0 + sx;
    ax2v[p] = ax2_0 + sx;
    inside[p] = iny && (ax1[p] >= 0.f) && (ax2v[p] < img_w);
  }

  int ng = s_ng;
  if (inside[0] || inside[3]) {     // inside is a contiguous interval in w
    for (int gi = 0; gi < ng; gi++) {
      int g = s_gl[gi];
      float ihh = __fadd_rn(__fsub_rn(fminf(ay2, s_gy2[g]), fmaxf(ay1, s_gy1[g])), 1.0f);
      ihh = fmaxf(ihh, 0.0f);
      if (ihh <= 0.0f) continue;                 // no vertical overlap: all 4 skip
      float gx1 = s_gx1[g], gx2 = s_gx2[g];
      float iwmax = __fadd_rn(__fsub_rn(fminf(ax2v[3], gx2), fmaxf(ax1[0], gx1)), 1.0f);
      if (iwmax <= 0.0f) continue;
      float ga = s_ga[g], gm = s_gm[g];
#pragma unroll
      for (int p = 0; p < 4; p++) {
        if (!inside[p]) continue;
        float iw = __fadd_rn(__fsub_rn(fminf(ax2v[p], gx2), fmaxf(ax1[p], gx1)), 1.0f);
        float inter = __fmul_rn(fmaxf(iw, 0.0f), ihh);
        if (inter <= 0.0f) continue;
        float ua = __fsub_rn(__fadd_rn(area, ga), inter);
        float tmx = __fmul_rn(mx[p], ua);        // max guard
        float bua = __fmul_rn(gm, ua);           // keep band
        if (inter > tmx * 0.9999995f || fabsf(inter - bua) <= bua * 3e-7f) {
          float v = __fdiv_rn(inter, ua);
          keep[p] = keep[p] || (v == gm);
          if (v > mx[p]) { mx[p] = v; amax[p] = g; }
        }
      }
    }
  }

  int L[4];
  float4 tgp[4];
#pragma unroll
  for (int p = 0; p < 4; p++) {
    L[p] = 2;
    if (inside[p]) L[p] = (keep[p] || mx[p] >= 0.7f) ? 1 : ((mx[p] < 0.3f) ? 0 : 2);
    tgp[p] = make_float4(0.f, 0.f, 0.f, 0.f);
    if (inside[p]) {
      int am = amax[p];
      float ecx = ax1[p] + 0.5f * ew, ecy = ay1 + 0.5f * eh;
      tgp[p].x = __fdividef(s_gcx[am] - ecx, ew);
      tgp[p].y = __fdividef(s_gcy[am] - ecy, eh);
      tgp[p].z = s_lw[am];
      tgp[p].w = s_lh[am];
    }
  }

  // ---- streaming vector stores: label fill, 4 target planes, 8 zero weight planes ----
  const size_t OFF1 = (size_t)BB * AA * HW;
  const size_t PL   = (size_t)BB * 36 * HW;
  size_t cb = ((size_t)b * 36 + a * 4) * HW + hw0;
  float4 z4 = make_float4(0.f, 0.f, 0.f, 0.f);
  __stcs(reinterpret_cast<float4*>(&out[((size_t)b * AA + a) * HW + hw0]),
         make_float4(-1.f, -1.f, -1.f, -1.f));
  float* tgt_o  = out + OFF1;
  float* inw_o  = out + OFF1 + PL;
  float* outw_o = out + OFF1 + 2 * PL;
  __stcs(reinterpret_cast<float4*>(&tgt_o[cb        ]), make_float4(tgp[0].x, tgp[1].x, tgp[2].x, tgp[3].x));
  __stcs(reinterpret_cast<float4*>(&tgt_o[cb +   HW ]), make_float4(tgp[0].y, tgp[1].y, tgp[2].y, tgp[3].y));
  __stcs(reinterpret_cast<float4*>(&tgt_o[cb + 2*HW ]), make_float4(tgp[0].z, tgp[1].z, tgp[2].z, tgp[3].z));
  __stcs(reinterpret_cast<float4*>(&tgt_o[cb + 3*HW ]), make_float4(tgp[0].w, tgp[1].w, tgp[2].w, tgp[3].w));
#pragma unroll
  for (int c = 0; c < 4; c++) __stcs(reinterpret_cast<float4*>(&inw_o [cb + (size_t)c * HW]), z4);
#pragma unroll
  for (int c = 0; c < 4; c++) __stcs(reinterpret_cast<float4*>(&outw_o[cb + (size_t)c * HW]), z4);

  // ---- RNG draws ----
  ull key[4];
  unsigned m[4];
  int cf = 0, cbg = 0, csf = 0, csb = 0;
#pragma unroll
  for (int p = 0; p < 4; p++) {
    m[p] = 0u; key[p] = 0ull;
    if (L[p] <= 1) {
      int t = (hw0 + p) * 9 + a;
      uint32_t key0 = L[p] ? kf0 : kb0, key1 = L[p] ? kf1 : kb1;
      uint32_t o0, o1;
      tf2x32(key0, key1, 0u, (uint32_t)(b * TT + t), o0, o1);
      m[p] = (o0 ^ o1) >> 9;
      key[p] = ((ull)m[p] << 16) | (unsigned)t;
      if (L[p] == 1) { cf++; if (m[p] < T_FG) csf++; }
      else           { cbg++; if (m[p] < T_BG) csb++; }
    }
  }

  // ---- warp-aggregated compaction ----
  int basef  = warp_alloc(&g_cnt_fg[b],  cf);
  int baseb  = warp_alloc(&g_cnt_bg[b],  cbg);
  int basesf = warp_alloc(&g_cnt_sfg[b], csf);
  int basesb = warp_alloc(&g_cnt_sbg[b], csb);
#pragma unroll
  for (int p = 0; p < 4; p++) {
    if (L[p] == 1) {
      g_cfg[(size_t)b * TT + basef++] = key[p];
      if (m[p] < T_FG) { if (basesf < SCAP) g_sfg[b*SCAP + basesf] = key[p]; basesf++; }
    } else if (L[p] == 0) {
      g_cbg[(size_t)b * TT + baseb++] = key[p];
      if (m[p] < T_BG) { if (basesb < SCAP) g_sbg[b*SCAP + basesb] = key[p]; basesb++; }
    }
  }
}

// ---------------- K3: exact k-smallest -> direct output scatter ----------------
__device__ __forceinline__ int blockInclScan(int local, int* s_wsum) {
  int lane = threadIdx.x & 31, wid = threadIdx.x >> 5;
  int v = local;
#pragma unroll
  for (int o = 1; o < 32; o <<= 1) { int n = __shfl_up_sync(FULLM, v, o); if (lane >= o) v += n; }
  if (lane == 31) s_wsum[wid] = v;
  __syncthreads();
  if (wid == 0) {
    int wv = s_wsum[lane];
#pragma unroll
    for (int o = 1; o < 32; o <<= 1) { int n = __shfl_up_sync(FULLM, wv, o); if (lane >= o) wv += n; }
    s_wsum[lane] = wv;
  }
  __syncthreads();
  return v + (wid ? s_wsum[wid-1] : 0);
}

__device__ __forceinline__ void scatter_keep(float* out, int b, int cls, float u, ull key) {
  const size_t OFF1 = (size_t)BB * AA * HW;
  const size_t PL   = (size_t)BB * 36 * HW;
  int t = (int)(key & 0xFFFFull);
  int a = t % 9, hw = t / 9;
  out[((size_t)b * AA + a) * HW + hw] = (float)cls;
  size_t cb = ((size_t)b * 36 + a * 4) * HW + hw;
  float* inw_o  = out + OFF1 + PL;
  float* outw_o = out + OFF1 + 2 * PL;
  if (cls) {
#pragma unroll
    for (int c = 0; c < 4; c++) inw_o[cb + (size_t)c * HW] = 1.0f;
  }
#pragma unroll
  for (int c = 0; c < 4; c++) outw_o[cb + (size_t)c * HW] = u;
}

__global__ void __launch_bounds__(1024) k3_select(float* __restrict__ out) {
  __shared__ unsigned s_hist[8192];   // fallback hist; shared-path: 2048 keys + 4096 bins
  __shared__ int s_wsum[32];
  __shared__ int s_sel[2];
  __shared__ int s_cnt;
  int b = blockIdx.x, cls = blockIdx.y, tid = threadIdx.x;

  int nfg = g_cnt_fg[b], nbg = g_cnt_bg[b];
  int kept_fg = min(nfg, FG_K);
  int kbg = RPN_BATCH_K - kept_fg;
  float u = 1.0f / (float)(kept_fg + min(nbg, kbg));
  int n = cls ? nfg : nbg;
  int k = cls ? FG_K : kbg;
  const ull* keys = (cls ? g_cfg : g_cbg) + (size_t)b * TT;

  if (n <= k) {                      // keep everything
    for (int i = tid; i < n; i += 1024) scatter_keep(out, b, cls, u, keys[i]);
    return;
  }

  // ---- fast shared-memory path ----
  int ns = cls ? g_cnt_sfg[b] : g_cnt_sbg[b];
  const ull* src = nullptr; int nm = 0;
  if (n <= SCAP)                        { src = keys; nm = n; }
  else if (ns >= k && ns <= SCAP)       { src = (cls ? g_sfg : g_sbg) + b*SCAP; nm = ns; }
  if (src) {
    ull* sk = reinterpret_cast<ull*>(s_hist);       // 2048 * 8B
    unsigned* h4 = s_hist + 4096;                   // 4096 bins
    for (int i = tid; i < nm; i += 1024) sk[i] = src[i];
    for (int i = tid; i < 4096; i += 1024) h4[i] = 0u;
    __syncthreads();
    for (int i = tid; i < nm; i += 1024)
      atomicAdd(&h4[(unsigned)(sk[i] >> 27)], 1u);  // top 12 bits of m
    __syncthreads();
    int base = tid * 4, local = 0;
#pragma unroll
    for (int j = 0; j < 4; j++) local += (int)h4[base + j];
    int incl = blockInclScan(local, s_wsum);
    int excl = incl - local;
    if (k > excl && k <= incl) {
      int c = excl;
      for (int j = 0; j < 4; j++) {
        int hh = (int)h4[base + j];
        if (c + hh >= k) { s_sel[0] = base + j; s_sel[1] = c; break; }
        c += hh;
      }
    }
    __syncthreads();
    int selbin = s_sel[0], cum = s_sel[1];
    for (int i = tid; i < nm; i += 1024) {
      ull key = sk[i];
      int bin = (int)(key >> 27);
      if (bin < selbin) {
        scatter_keep(out, b, cls, u, key);
      } else if (bin == selbin) {
        int lr = 0;
        for (int j = 0; j < nm; j++) {
          ull kj = sk[j];
          lr += ((int)(kj >> 27) == selbin) && (kj < key);
        }
        if (cum + lr < k) scatter_keep(out, b, cls, u, key);
      }
    }
    return;
  }

  // ---- fallback: global multi-level radix select (rare) ----
  ull* s_keys = reinterpret_cast<ull*>(s_hist);
  ull prefix = 0ull;
  int kk = k, shift = 26;
  for (int lvl = 0; ; lvl++) {
    shift = 26 - 13 * lvl;
    for (int i = tid; i < 8192; i += 1024) s_hist[i] = 0u;
    __syncthreads();
    for (int i = tid; i < n; i += 1024) {
      ull key = keys[i];
      if (lvl == 0 || (key >> (shift + 13)) == prefix)
        atomicAdd(&s_hist[(unsigned)(key >> shift) & 8191u], 1u);
    }
    __syncthreads();
    {
      int base = tid * 8, local = 0;
#pragma unroll
      for (int j = 0; j < 8; j++) local += (int)s_hist[base + j];
      int incl = blockInclScan(local, s_wsum);
      int excl = incl - local;
      if (kk > excl && kk <= incl) {
        int c = excl;
        for (int j = 0; j < 8; j++) {
          int hh = (int)s_hist[base + j];
          if (c + hh >= kk) { s_sel[0] = base + j; s_sel[1] = c; break; }
          c += hh;
        }
      }
      __syncthreads();
    }
    prefix = (prefix << 13) | (unsigned)s_sel[0];
    kk -= s_sel[1];
    int bc = (int)s_hist[s_sel[0]];
    __syncthreads();
    if (bc <= 4096 || shift == 0) break;
  }
  if (tid == 0) s_cnt = 0;
  __syncthreads();
  for (int i = tid; i < n; i += 1024) {
    ull key = keys[i];
    ull hi = key >> shift;
    if (hi < prefix) scatter_keep(out, b, cls, u, key);
    else if (hi == prefix) {
      int j = atomicAdd(&s_cnt, 1);
      s_keys[j] = key;
    }
  }
  __syncthreads();
  int cnt = s_cnt;
  for (int jj = tid; jj < cnt; jj += 1024) {
    ull kj = s_keys[jj];
    int r = 0;
    for (int i = 0; i < cnt; i++) r += (s_keys[i] < kj);
    if (r < kk) scatter_keep(out, b, cls, u, kj);
  }
}

// ---------------- host ----------------
extern "C" void kernel_launch(void* const* d_in, const int* in_sizes, int n_in,
                              void* d_out, int out_size) {
  const float* gt     = (const float*)d_in[1];   // gt_boxes [32,20,5]
  const float* iminfo = (const float*)d_in[2];   // im_info [32,3]
  float* out = (float*)d_out;

  uint32_t kf0, kf1, kb0, kb1;
  tf2x32(0u, 42u, 0u, 0u, kf0, kf1);
  tf2x32(0u, 42u, 0u, 1u, kb0, kb1);

  k0_gtmax <<<BB, 192>>>(gt, iminfo);
  k2_main  <<<dim3(5, AA, BB), 320>>>(gt, iminfo, kf0, kf1, kb0, kb1, out);
  k3_select<<<dim3(BB, 2), 1024>>>(out);
}